// round 9
// baseline (speedup 1.0000x reference)
#include <cuda_runtime.h>
#include <math.h>
#include <stdint.h>

#define BATCH 8
#define LSEQ  1024
#define HID   768
#define NH    12
#define DH    64
#define MLPD  3072
#define MROWS (BATCH*LSEQ)    // 8192
#define NHEADS_TOT (BATCH*NH) // 96

// ---------------- static scratch ----------------
__device__ float g_QK [(size_t)MROWS*2*HID];   // QK output; later reused as split-K partials
__device__ float g_Qh [MROWS*HID];
__device__ float g_Kh [MROWS*HID];
__device__ float g_Ch [MROWS*HID];
__device__ float g_Ctx[MROWS*HID];
__device__ float g_y  [MROWS*HID];
__device__ float g_x1 [MROWS*HID];
__device__ float g_Hf [(size_t)MROWS*MLPD];
__device__ float g_y2 [MROWS*HID];
__device__ float g_xr [MROWS*HID];
__device__ float g_Wqk[HID*2*HID];
__device__ float g_Wor[HID*HID];
__device__ float g_W1r[HID*MLPD];
__device__ float g_W2r[MLPD*HID];

// ---------------- helpers ----------------
__device__ __forceinline__ float gelu_f(float v) {
    return 0.5f * v * (1.0f + erff(v * 0.7071067811865475f));
}

__device__ __forceinline__ uint32_t f2tf32(float f) {
    uint32_t u;
    asm("cvt.rna.tf32.f32 %0, %1;" : "=r"(u) : "f"(f));
    return u;
}
__device__ __forceinline__ float rndtf(float f) { return __uint_as_float(f2tf32(f)); }

__device__ __forceinline__ void mma_tf32(float* d, const uint32_t* a, const uint32_t* b) {
    asm volatile(
        "mma.sync.aligned.m16n8k8.row.col.f32.tf32.tf32.f32 "
        "{%0,%1,%2,%3}, {%4,%5,%6,%7}, {%8,%9}, {%0,%1,%2,%3};\n"
        : "+f"(d[0]), "+f"(d[1]), "+f"(d[2]), "+f"(d[3])
        : "r"(a[0]), "r"(a[1]), "r"(a[2]), "r"(a[3]),
          "r"(b[0]), "r"(b[1]));
}

__device__ __forceinline__ void ldsm4(uint32_t* r, uint32_t addr) {
    asm volatile("ldmatrix.sync.aligned.m8n8.x4.shared.b16 {%0,%1,%2,%3}, [%4];"
        : "=r"(r[0]), "=r"(r[1]), "=r"(r[2]), "=r"(r[3]) : "r"(addr));
}

__device__ __forceinline__ void cp16(uint32_t dst, const void* src) {
    asm volatile("cp.async.cg.shared.global [%0], [%1], 16;\n" :: "r"(dst), "l"(src));
}
__device__ __forceinline__ void cp_commit() {
    asm volatile("cp.async.commit_group;\n");
}
template<int N>
__device__ __forceinline__ void cp_wait() {
    asm volatile("cp.async.wait_group %0;\n" :: "n"(N));
}

enum { EPI_NONE = 0, EPI_RES = 1, EPI_BIAS_GELU = 2, EPI_BIAS_RES = 3 };

// BK=32, 2-stage overlap pipeline
#define AS_STR 36
#define BS_STR 136
#define GEMM_SMEM_BYTES (2 * (128 * AS_STR + 32 * BS_STR) * 4)

// ---------------- TF32 tensor-core GEMM: C = A(MxK) @ B(KxN) ----------------
template<int EPI, bool ROUND_OUT>
__global__ __launch_bounds__(256, 2) void gemm_tc(
    const float* __restrict__ A, const float* __restrict__ B, float* __restrict__ C,
    const float* __restrict__ bias, const float* __restrict__ res,
    int M, int N, int K)
{
    extern __shared__ uint32_t dynsmem[];
    uint32_t* As = dynsmem;                       // [2][128][AS_STR]
    uint32_t* Bs = dynsmem + 2 * 128 * AS_STR;    // [2][32][BS_STR]
    const uint32_t sA = (uint32_t)__cvta_generic_to_shared(As);
    const uint32_t sB = (uint32_t)__cvta_generic_to_shared(Bs);

    const int tid  = threadIdx.x;
    const int lane = tid & 31;
    const int warp = tid >> 5;
    const int grp  = lane >> 2;
    const int tg   = lane & 3;
    const int wm   = (warp >> 2) * 64;
    const int wn   = (warp & 3) * 32;
    const int bx   = blockIdx.x;
    const int by   = blockIdx.y;

    const int rl = lane & 15;
    const int cb = (lane >> 4) << 2;

    const float* Abase = A + (size_t)(by * 128) * K;
    const float* Bbase = B + bx * 128;

    float acc[4][4][4];
    #pragma unroll
    for (int i = 0; i < 4; i++)
        #pragma unroll
        for (int j = 0; j < 4; j++)
            #pragma unroll
            for (int r = 0; r < 4; r++) acc[i][j][r] = 0.0f;

    const int ntiles = K >> 5;

    auto issue = [&](int t) {
        const int st = t & 1;
        const int k0 = t * 32;
        const uint32_t aoff = sA + (uint32_t)(st * 128 * AS_STR) * 4;
        const uint32_t boff = sB + (uint32_t)(st * 32 * BS_STR) * 4;
        #pragma unroll
        for (int i = 0; i < 4; i++) {
            int f = tid + 256 * i;
            int ar = f >> 3, ac = (f & 7) * 4;
            cp16(aoff + (uint32_t)(ar * AS_STR + ac) * 4, Abase + (size_t)ar * K + k0 + ac);
        }
        #pragma unroll
        for (int i = 0; i < 4; i++) {
            int f = tid + 256 * i;
            int br = f >> 5, bc = (f & 31) * 4;
            cp16(boff + (uint32_t)(br * BS_STR + bc) * 4, Bbase + (size_t)(k0 + br) * N + bc);
        }
        cp_commit();
    };

    issue(0);

    for (int t = 0; t < ntiles; t++) {
        cp_wait<0>();
        __syncthreads();
        if (t + 1 < ntiles) issue(t + 1);   // load next tile under this tile's compute

        const int cur = t & 1;
        const uint32_t aBase = sA + (uint32_t)(cur * 128 * AS_STR) * 4;
        const uint32_t* Bc = Bs + cur * 32 * BS_STR;

        #pragma unroll
        for (int kk = 0; kk < 32; kk += 8) {
            uint32_t a[4][4], b[4][2];
            #pragma unroll
            for (int mt = 0; mt < 4; mt++)
                ldsm4(a[mt], aBase + (uint32_t)((wm + mt * 16 + rl) * AS_STR + kk + cb) * 4);
            #pragma unroll
            for (int nt = 0; nt < 4; nt++) {
                const int c = wn + nt * 8 + grp;
                b[nt][0] = Bc[(kk + tg) * BS_STR + c];
                b[nt][1] = Bc[(kk + tg + 4) * BS_STR + c];
            }
            #pragma unroll
            for (int mt = 0; mt < 4; mt++)
                #pragma unroll
                for (int nt = 0; nt < 4; nt++)
                    mma_tf32(acc[mt][nt], a[mt], b[nt]);
        }
    }

    #pragma unroll
    for (int mt = 0; mt < 4; mt++) {
        #pragma unroll
        for (int nt = 0; nt < 4; nt++) {
            const int r0 = by * 128 + wm + mt * 16 + grp;
            const int c0 = bx * 128 + wn + nt * 8 + tg * 2;
            float v0 = acc[mt][nt][0], v1 = acc[mt][nt][1];
            float v2 = acc[mt][nt][2], v3 = acc[mt][nt][3];
            if (EPI == EPI_RES) {
                const float2 r0v = *(const float2*)&res[(size_t)r0 * N + c0];
                const float2 r1v = *(const float2*)&res[(size_t)(r0 + 8) * N + c0];
                v0 += r0v.x; v1 += r0v.y; v2 += r1v.x; v3 += r1v.y;
            }
            if (EPI == EPI_BIAS_GELU) {
                const float2 bv = *(const float2*)&bias[c0];
                v0 = gelu_f(v0 + bv.x); v1 = gelu_f(v1 + bv.y);
                v2 = gelu_f(v2 + bv.x); v3 = gelu_f(v3 + bv.y);
            }
            if (EPI == EPI_BIAS_RES) {
                const float2 bv = *(const float2*)&bias[c0];
                const float2 r0v = *(const float2*)&res[(size_t)r0 * N + c0];
                const float2 r1v = *(const float2*)&res[(size_t)(r0 + 8) * N + c0];
                v0 += bv.x + r0v.x; v1 += bv.y + r0v.y;
                v2 += bv.x + r1v.x; v3 += bv.y + r1v.y;
            }
            if (ROUND_OUT) {
                v0 = rndtf(v0); v1 = rndtf(v1); v2 = rndtf(v2); v3 = rndtf(v3);
            }
            float2 w0 = {v0, v1}, w1 = {v2, v3};
            *(float2*)&C[(size_t)r0 * N + c0] = w0;
            *(float2*)&C[(size_t)(r0 + 8) * N + c0] = w1;
        }
    }
}

// ---------------- split-K=2 partial GEMM ----------------
__global__ __launch_bounds__(256, 2) void gemm_splitk(
    const float* __restrict__ A, const float* __restrict__ B, float* __restrict__ Cp,
    int M, int N, int lda, int Khalf)
{
    extern __shared__ uint32_t dynsmem[];
    uint32_t* As = dynsmem;
    uint32_t* Bs = dynsmem + 2 * 128 * AS_STR;
    const uint32_t sA = (uint32_t)__cvta_generic_to_shared(As);
    const uint32_t sB = (uint32_t)__cvta_generic_to_shared(Bs);

    const int tid  = threadIdx.x;
    const int lane = tid & 31;
    const int warp = tid >> 5;
    const int grp  = lane >> 2;
    const int tg   = lane & 3;
    const int wm   = (warp >> 2) * 64;
    const int wn   = (warp & 3) * 32;
    const int bx   = blockIdx.x;
    const int by   = blockIdx.y;
    const int z    = blockIdx.z;

    const int rl = lane & 15;
    const int cb = (lane >> 4) << 2;

    const float* Abase = A + (size_t)(by * 128) * lda + (size_t)z * Khalf;
    const float* Bbase = B + (size_t)z * Khalf * N + bx * 128;

    float acc[4][4][4];
    #pragma unroll
    for (int i = 0; i < 4; i++)
        #pragma unroll
        for (int j = 0; j < 4; j++)
            #pragma unroll
            for (int r = 0; r < 4; r++) acc[i][j][r] = 0.0f;

    const int ntiles = Khalf >> 5;

    auto issue = [&](int t) {
        const int st = t & 1;
        const int k0 = t * 32;
        const uint32_t aoff = sA + (uint32_t)(st * 128 * AS_STR) * 4;
        const uint32_t boff = sB + (uint32_t)(st * 32 * BS_STR) * 4;
        #pragma unroll
        for (int i = 0; i < 4; i++) {
            int f = tid + 256 * i;
            int ar = f >> 3, ac = (f & 7) * 4;
            cp16(aoff + (uint32_t)(ar * AS_STR + ac) * 4, Abase + (size_t)ar * lda + k0 + ac);
        }
        #pragma unroll
        for (int i = 0; i < 4; i++) {
            int f = tid + 256 * i;
            int br = f >> 5, bc = (f & 31) * 4;
            cp16(boff + (uint32_t)(br * BS_STR + bc) * 4, Bbase + (size_t)(k0 + br) * N + bc);
        }
        cp_commit();
    };

    issue(0);

    for (int t = 0; t < ntiles; t++) {
        cp_wait<0>();
        __syncthreads();
        if (t + 1 < ntiles) issue(t + 1);

        const int cur = t & 1;
        const uint32_t aBase = sA + (uint32_t)(cur * 128 * AS_STR) * 4;
        const uint32_t* Bc = Bs + cur * 32 * BS_STR;

        #pragma unroll
        for (int kk = 0; kk < 32; kk += 8) {
            uint32_t a[4][4], b[4][2];
            #pragma unroll
            for (int mt = 0; mt < 4; mt++)
                ldsm4(a[mt], aBase + (uint32_t)((wm + mt * 16 + rl) * AS_STR + kk + cb) * 4);
            #pragma unroll
            for (int nt = 0; nt < 4; nt++) {
                const int c = wn + nt * 8 + grp;
                b[nt][0] = Bc[(kk + tg) * BS_STR + c];
                b[nt][1] = Bc[(kk + tg + 4) * BS_STR + c];
            }
            #pragma unroll
            for (int mt = 0; mt < 4; mt++)
                #pragma unroll
                for (int nt = 0; nt < 4; nt++)
                    mma_tf32(acc[mt][nt], a[mt], b[nt]);
        }
    }

    float* Cz = Cp + (size_t)z * M * N;
    #pragma unroll
    for (int mt = 0; mt < 4; mt++) {
        #pragma unroll
        for (int nt = 0; nt < 4; nt++) {
            const int r0 = by * 128 + wm + mt * 16 + grp;
            const int c0 = bx * 128 + wn + nt * 8 + tg * 2;
            float2 w0 = {acc[mt][nt][0], acc[mt][nt][1]};
            float2 w1 = {acc[mt][nt][2], acc[mt][nt][3]};
            *(float2*)&Cz[(size_t)r0 * N + c0] = w0;
            *(float2*)&Cz[(size_t)(r0 + 8) * N + c0] = w1;
        }
    }
}

// ---------------- split-K reduce kernels ----------------
__global__ void reduce_res_k(const float4* __restrict__ p, const float4* __restrict__ res,
                             float4* __restrict__ y) {
    int i = blockIdx.x * blockDim.x + threadIdx.x;
    if (i >= MROWS * HID / 4) return;
    float4 a = p[i], b = p[i + MROWS * HID / 4], r = res[i];
    float4 o = {a.x + b.x + r.x, a.y + b.y + r.y, a.z + b.z + r.z, a.w + b.w + r.w};
    y[i] = o;
}

__global__ void reduce_bias_res_k(const float4* __restrict__ p, const float* __restrict__ bias,
                                  const float4* __restrict__ res, float4* __restrict__ y) {
    int i = blockIdx.x * blockDim.x + threadIdx.x;
    if (i >= MROWS * HID / 4) return;
    float4 a = p[i], b = p[i + MROWS * HID / 4], r = res[i];
    const float4 bv = *(const float4*)&bias[(i % (HID / 4)) * 4];
    float4 o = {a.x + b.x + r.x + bv.x, a.y + b.y + r.y + bv.y,
                a.z + b.z + r.z + bv.z, a.w + b.w + r.w + bv.w};
    y[i] = o;
}

// ---------------- operand pre-rounding ----------------
#define NQK (HID*HID/4)
#define NWO (HID*HID/4)
#define NW1 (HID*MLPD/4)
#define NW2 (MLPD*HID/4)
#define NWB (NWO + NW1 + NW2)

__device__ __forceinline__ float4 rnd4(float4 v) {
    v.x = rndtf(v.x); v.y = rndtf(v.y); v.z = rndtf(v.z); v.w = rndtf(v.w);
    return v;
}

__global__ void round_wa_k(const float* __restrict__ Wq, const float* __restrict__ Wk) {
    int i = blockIdx.x * blockDim.x + threadIdx.x;
    if (i >= NQK) return;
    int k = i / (HID / 4), c = (i % (HID / 4)) * 4;
    *(float4*)(g_Wqk + (size_t)k * (2 * HID) + c)       = rnd4(*(const float4*)(Wq + (size_t)k * HID + c));
    *(float4*)(g_Wqk + (size_t)k * (2 * HID) + HID + c) = rnd4(*(const float4*)(Wk + (size_t)k * HID + c));
}

__global__ void round_wb_k(const float* __restrict__ Wo, const float* __restrict__ W1,
                           const float* __restrict__ W2) {
    int i = blockIdx.x * blockDim.x + threadIdx.x;
    if (i >= NWB) return;
    if (i < NWO) { ((float4*)g_Wor)[i] = rnd4(((const float4*)Wo)[i]); return; }
    i -= NWO;
    if (i < NW1) { ((float4*)g_W1r)[i] = rnd4(((const float4*)W1)[i]); return; }
    i -= NW1;
    ((float4*)g_W2r)[i] = rnd4(((const float4*)W2)[i]);
}

__global__ void round_x_k(const float4* __restrict__ in, float4* __restrict__ out, int n4) {
    int i = blockIdx.x * blockDim.x + threadIdx.x;
    if (i >= n4) return;
    out[i] = rnd4(in[i]);
}

// ---------------- permutes ----------------
__global__ void to_head2_k(const float* __restrict__ QK,
                           float* __restrict__ Qh, float* __restrict__ Kh) {
    int idx = blockIdx.x * blockDim.x + threadIdx.x;
    if (idx >= MROWS * HID) return;
    int d = idx & 63;
    int l = (idx >> 6) & 1023;
    int z = idx >> 16;
    int n = z % NH, b = z / NH;
    const size_t src = (size_t)(b * LSEQ + l) * (2 * HID) + d * NH + n;
    Qh[idx] = QK[src];
    Kh[idx] = QK[src + HID];
}

__global__ void from_head_k(const float* __restrict__ Xh, float* __restrict__ X) {
    int idx = blockIdx.x * blockDim.x + threadIdx.x;
    if (idx >= MROWS * HID) return;
    int h = idx % HID;
    int row = idx / HID;
    int l = row & 1023, b = row >> 10;
    int d = h / NH, n = h % NH;
    X[idx] = rndtf(Xh[((size_t)(b * NH + n) * LSEQ + l) * DH + d]);
}

// ---------------- fused flash attention (TF32 mma + LDSM) ----------------
#define QS_STR 68
#define KS_STR 68
#define PS_STR 132
#define ATTN_SMEM_WORDS (128*QS_STR + 128*KS_STR + 128*PS_STR + 128 + 128 + 512 + 512)
#define ATTN_SMEM_BYTES (ATTN_SMEM_WORDS * 4)

__global__ __launch_bounds__(256) void attn_fused(
    const float* __restrict__ Qh, const float* __restrict__ Kh, float* __restrict__ Ch)
{
    extern __shared__ uint32_t sm[];
    uint32_t* Qs = sm;
    uint32_t* Ks = Qs + 128 * QS_STR;
    uint32_t* Ps = Ks + 128 * KS_STR;
    float* Mrow  = (float*)(Ps + 128 * PS_STR);
    float* Srow  = Mrow + 128;
    float* red1  = Srow + 128;
    float* red2  = red1 + 512;

    const uint32_t qAddr = (uint32_t)__cvta_generic_to_shared(Qs);
    const uint32_t kAddr = (uint32_t)__cvta_generic_to_shared(Ks);
    const uint32_t pAddr = (uint32_t)__cvta_generic_to_shared(Ps);

    const int z   = blockIdx.y;
    const int l0  = blockIdx.x * 128;
    const int tid = threadIdx.x;
    const int lane = tid & 31;
    const int warp = tid >> 5;
    const int grp  = lane >> 2;
    const int tg   = lane & 3;
    const int wm   = (warp >> 2) * 64;
    const int wn   = (warp & 3) * 32;
    const int wn2  = (warp & 3) * 16;
    const int wc   = warp & 3;
    const int rl   = lane & 15;
    const int cbo  = (lane >> 4) << 2;

    const float* Qbase = Qh + ((size_t)z * LSEQ + l0) * DH;
    const float* Kbase = Kh + (size_t)z * LSEQ * DH;

    if (tid < 128) { Mrow[tid] = -3.0e38f; Srow[tid] = 0.0f; }

    #pragma unroll
    for (int i = 0; i < 8; i++) {
        int f = tid + 256 * i;
        int r = f >> 4, c = (f & 15) * 4;
        float4 q = *(const float4*)(Qbase + r * DH + c);
        Qs[r * QS_STR + c + 0] = f2tf32(0.125f * q.x);
        Qs[r * QS_STR + c + 1] = f2tf32(0.125f * q.y);
        Qs[r * QS_STR + c + 2] = f2tf32(0.125f * q.z);
        Qs[r * QS_STR + c + 3] = f2tf32(0.125f * q.w);
    }

    float acc_o[4][2][4];
    #pragma unroll
    for (int i = 0; i < 4; i++)
        #pragma unroll
        for (int j = 0; j < 2; j++)
            #pragma unroll
            for (int r = 0; r < 4; r++) acc_o[i][j][r] = 0.0f;

    __syncthreads();

    for (int mtile = 0; mtile < LSEQ / 128; mtile++) {
        const float* Kt = Kbase + (size_t)mtile * 128 * DH;
        #pragma unroll
        for (int i = 0; i < 8; i++) {
            int f = tid + 256 * i;
            int r = f >> 4, c = (f & 15) * 4;
            float4 k4 = *(const float4*)(Kt + r * DH + c);
            Ks[r * KS_STR + c + 0] = f2tf32(k4.x);
            Ks[r * KS_STR + c + 1] = f2tf32(k4.y);
            Ks[r * KS_STR + c + 2] = f2tf32(k4.z);
            Ks[r * KS_STR + c + 3] = f2tf32(k4.w);
        }
        __syncthreads();

        float s[4][4][4];
        #pragma unroll
        for (int i = 0; i < 4; i++)
            #pragma unroll
            for (int j = 0; j < 4; j++)
                #pragma unroll
                for (int r = 0; r < 4; r++) s[i][j][r] = 0.0f;

        #pragma unroll
        for (int kk = 0; kk < DH; kk += 8) {
            uint32_t a[4][4], b[4][2];
            #pragma unroll
            for (int mt = 0; mt < 4; mt++)
                ldsm4(a[mt], qAddr + (uint32_t)((wm + mt * 16 + rl) * QS_STR + kk + cbo) * 4);
            #pragma unroll
            for (int p = 0; p < 2; p++) {
                uint32_t t4[4];
                ldsm4(t4, kAddr + (uint32_t)((wn + p * 16 + rl) * KS_STR + kk + cbo) * 4);
                b[2 * p][0]     = t4[0];
                b[2 * p + 1][0] = t4[1];
                b[2 * p][1]     = t4[2];
                b[2 * p + 1][1] = t4[3];
            }
            #pragma unroll
            for (int mt = 0; mt < 4; mt++)
                #pragma unroll
                for (int nt = 0; nt < 4; nt++)
                    mma_tf32(s[mt][nt], a[mt], b[nt]);
        }

        #pragma unroll
        for (int mt = 0; mt < 4; mt++) {
            float mlo = -3.0e38f, mhi = -3.0e38f;
            #pragma unroll
            for (int nt = 0; nt < 4; nt++) {
                mlo = fmaxf(mlo, fmaxf(s[mt][nt][0], s[mt][nt][1]));
                mhi = fmaxf(mhi, fmaxf(s[mt][nt][2], s[mt][nt][3]));
            }
            mlo = fmaxf(mlo, __shfl_xor_sync(0xffffffffu, mlo, 1));
            mlo = fmaxf(mlo, __shfl_xor_sync(0xffffffffu, mlo, 2));
            mhi = fmaxf(mhi, __shfl_xor_sync(0xffffffffu, mhi, 1));
            mhi = fmaxf(mhi, __shfl_xor_sync(0xffffffffu, mhi, 2));
            if (tg == 0) {
                red1[(wm + mt * 16 + grp) * 4 + wc]     = mlo;
                red1[(wm + mt * 16 + grp + 8) * 4 + wc] = mhi;
            }
        }
        __syncthreads();

        float newlo[4], newhi[4], scllo[4], sclhi[4];
        #pragma unroll
        for (int mt = 0; mt < 4; mt++) {
            const int rlo = wm + mt * 16 + grp;
            const int rhi = rlo + 8;
            float4 v1 = *(const float4*)&red1[rlo * 4];
            float4 v2 = *(const float4*)&red1[rhi * 4];
            float tlo = fmaxf(fmaxf(v1.x, v1.y), fmaxf(v1.z, v1.w));
            float thi = fmaxf(fmaxf(v2.x, v2.y), fmaxf(v2.z, v2.w));
            float oldlo = Mrow[rlo], oldhi = Mrow[rhi];
            float nlo = fmaxf(oldlo, tlo), nhi = fmaxf(oldhi, thi);
            newlo[mt] = nlo; newhi[mt] = nhi;
            scllo[mt] = __expf(oldlo - nlo);
            sclhi[mt] = __expf(oldhi - nhi);

            float pslo = 0.0f, pshi = 0.0f;
            #pragma unroll
            for (int nt = 0; nt < 4; nt++) {
                const int c = wn + nt * 8 + 2 * tg;
                float p0 = __expf(s[mt][nt][0] - nlo);
                float p1 = __expf(s[mt][nt][1] - nlo);
                float p2 = __expf(s[mt][nt][2] - nhi);
                float p3 = __expf(s[mt][nt][3] - nhi);
                Ps[rlo * PS_STR + c]     = f2tf32(p0);
                Ps[rlo * PS_STR + c + 1] = f2tf32(p1);
                Ps[rhi * PS_STR + c]     = f2tf32(p2);
                Ps[rhi * PS_STR + c + 1] = f2tf32(p3);
                pslo += p0 + p1;
                pshi += p2 + p3;
            }
            pslo += __shfl_xor_sync(0xffffffffu, pslo, 1);
            pslo += __shfl_xor_sync(0xffffffffu, pslo, 2);
            pshi += __shfl_xor_sync(0xffffffffu, pshi, 1);
            pshi += __shfl_xor_sync(0xffffffffu, pshi, 2);
            if (tg == 0) {
                red2[rlo * 4 + wc] = pslo;
                red2[rhi * 4 + wc] = pshi;
            }
            #pragma unroll
            for (int nt2 = 0; nt2 < 2; nt2++) {
                acc_o[mt][nt2][0] *= scllo[mt];
                acc_o[mt][nt2][1] *= scllo[mt];
                acc_o[mt][nt2][2] *= sclhi[mt];
                acc_o[mt][nt2][3] *= sclhi[mt];
            }
        }
        __syncthreads();

        if (wc == 0 && tg == 0) {
            #pragma unroll
            for (int mt = 0; mt < 4; mt++) {
                const int rlo = wm + mt * 16 + grp;
                const int rhi = rlo + 8;
                float4 w1 = *(const float4*)&red2[rlo * 4];
                float4 w2 = *(const float4*)&red2[rhi * 4];
                Srow[rlo] = Srow[rlo] * scllo[mt] + (w1.x + w1.y + w1.z + w1.w);
                Srow[rhi] = Srow[rhi] * sclhi[mt] + (w2.x + w2.y + w2.z + w2.w);
                Mrow[rlo] = newlo[mt];
                Mrow[rhi] = newhi[mt];
            }
        }

        #pragma unroll
        for (int kk = 0; kk < 128; kk += 8) {
            uint32_t a[4][4], b[2][2];
            #pragma unroll
            for (int mt = 0; mt < 4; mt++)
                ldsm4(a[mt], pAddr + (uint32_t)((wm + mt * 16 + rl) * PS_STR + kk + cbo) * 4);
            #pragma unroll
            for (int nt2 = 0; nt2 < 2; nt2++) {
                const int c = wn2 + nt2 * 8 + grp;
                b[nt2][0] = Ks[(kk + tg) * KS_STR + c];
                b[nt2][1] = Ks[(kk + tg + 4) * KS_STR + c];
            }
            #pragma unroll
            for (int mt = 0; mt < 4; mt++)
                #pragma unroll
                for (int nt2 = 0; nt2 < 2; nt2++)
                    mma_tf32(acc_o[mt][nt2], a[mt], b[nt2]);
        }
        __syncthreads();
    }

    #pragma unroll
    for (int mt = 0; mt < 4; mt++) {
        const int rlo = wm + mt * 16 + grp;
        const int rhi = rlo + 8;
        const float ilo = 1.0f / Srow[rlo];
        const float ihi = 1.0f / Srow[rhi];
        #pragma unroll
        for (int nt2 = 0; nt2 < 2; nt2++) {
            const int c = wn2 + nt2 * 8 + 2 * tg;
            float2 o0 = {acc_o[mt][nt2][0] * ilo, acc_o[mt][nt2][1] * ilo};
            float2 o1 = {acc_o[mt][nt2][2] * ihi, acc_o[mt][nt2][3] * ihi};
            *(float2*)&Ch[((size_t)z * LSEQ + l0 + rlo) * DH + c] = o0;
            *(float2*)&Ch[((size_t)z * LSEQ + l0 + rhi) * DH + c] = o1;
        }
    }
}

// ---------------- layernorm ----------------
template<bool RND>
__global__ __launch_bounds__(256) void layernorm_rows_k(
    const float* __restrict__ X, const float* __restrict__ g,
    const float* __restrict__ be, float* __restrict__ Y)
{
    const int row = blockIdx.x;
    const float* x = X + (size_t)row * HID;
    float* y = Y + (size_t)row * HID;
    const int tid = threadIdx.x;
    __shared__ float shs[8], shss[8];

    float s = 0.0f, ss = 0.0f;
    for (int c = tid; c < HID; c += 256) {
        float v = x[c];
        s += v;
        ss = fmaf(v, v, ss);
    }
    #pragma unroll
    for (int o = 16; o; o >>= 1) {
        s  += __shfl_xor_sync(0xffffffffu, s, o);
        ss += __shfl_xor_sync(0xffffffffu, ss, o);
    }
    if ((tid & 31) == 0) { shs[tid >> 5] = s; shss[tid >> 5] = ss; }
    __syncthreads();
    if (tid == 0) {
        float a = 0.0f, b = 0.0f;
        #pragma unroll
        for (int i = 0; i < 8; i++) { a += shs[i]; b += shss[i]; }
        shs[0] = a; shss[0] = b;
    }
    __syncthreads();
    const float mu  = shs[0]  * (1.0f / HID);
    const float var = shss[0] * (1.0f / HID) - mu * mu;
    const float inv = rsqrtf(var + 1e-5f);
    for (int c = tid; c < HID; c += 256) {
        float v = (x[c] - mu) * inv * g[c] + be[c];
        y[c] = RND ? rndtf(v) : v;
    }
}

// ---------------- host launch ----------------
extern "C" void kernel_launch(void* const* d_in, const int* in_sizes, int n_in,
                              void* d_out, int out_size)
{
    const float* x   = (const float*)d_in[0];
    const float* Wq  = (const float*)d_in[1];
    const float* Wk  = (const float*)d_in[2];
    // d_in[3] = Wv: unused (ctx contracts with K in the reference)
    const float* Wo  = (const float*)d_in[4];
    const float* W1  = (const float*)d_in[5];
    const float* b1  = (const float*)d_in[6];
    const float* W2  = (const float*)d_in[7];
    const float* b2  = (const float*)d_in[8];
    const float* g1  = (const float*)d_in[9];
    const float* be1 = (const float*)d_in[10];
    const float* g2  = (const float*)d_in[11];
    const float* be2 = (const float*)d_in[12];
    float* out = (float*)d_out;

    float *QK, *Qh, *Kh, *Ch, *Ctx, *y, *x1, *Hf, *y2;
    float *xr, *Wqk, *Wor, *W1r, *W2r;
    cudaGetSymbolAddress((void**)&QK, g_QK);
    cudaGetSymbolAddress((void**)&Qh, g_Qh);
    cudaGetSymbolAddress((void**)&Kh, g_Kh);
    cudaGetSymbolAddress((void**)&Ch, g_Ch);
    cudaGetSymbolAddress((void**)&Ctx,g_Ctx);
    cudaGetSymbolAddress((void**)&y,  g_y);
    cudaGetSymbolAddress((void**)&x1, g_x1);
    cudaGetSymbolAddress((void**)&Hf, g_Hf);
    cudaGetSymbolAddress((void**)&y2, g_y2);
    cudaGetSymbolAddress((void**)&xr, g_xr);
    cudaGetSymbolAddress((void**)&Wqk,g_Wqk);
    cudaGetSymbolAddress((void**)&Wor,g_Wor);
    cudaGetSymbolAddress((void**)&W1r,g_W1r);
    cudaGetSymbolAddress((void**)&W2r,g_W2r);

    static bool attrs_set = false;
    if (!attrs_set) {
        cudaFuncSetAttribute(attn_fused, cudaFuncAttributeMaxDynamicSharedMemorySize, ATTN_SMEM_BYTES);
        cudaFuncSetAttribute(gemm_tc<EPI_NONE, false>,      cudaFuncAttributeMaxDynamicSharedMemorySize, GEMM_SMEM_BYTES);
        cudaFuncSetAttribute(gemm_tc<EPI_BIAS_GELU, true>,  cudaFuncAttributeMaxDynamicSharedMemorySize, GEMM_SMEM_BYTES);
        cudaFuncSetAttribute(gemm_splitk,                   cudaFuncAttributeMaxDynamicSharedMemorySize, GEMM_SMEM_BYTES);
        attrs_set = true;
    }

    const int nperm = MROWS * HID;
    const int n4 = MROWS * HID / 4;

    // ---- operand pre-rounding ----
    round_wa_k<<<(NQK + 255) / 256, 256>>>(Wq, Wk);
    round_wb_k<<<(NWB + 255) / 256, 256>>>(Wo, W1, W2);
    round_x_k<<<(n4 + 255) / 256, 256>>>((const float4*)x, (float4*)xr, n4);

    // ---- QK merged GEMM ----
    gemm_tc<EPI_NONE, false><<<dim3(2 * HID / 128, MROWS / 128), 256, GEMM_SMEM_BYTES>>>(
        xr, Wqk, QK, nullptr, nullptr, MROWS, 2 * HID, HID);

    to_head2_k<<<(nperm + 255) / 256, 256>>>(QK, Qh, Kh);

    attn_fused<<<dim3(LSEQ / 128, NHEADS_TOT), 256, ATTN_SMEM_BYTES>>>(Qh, Kh, Ch);
    from_head_k<<<(nperm + 255) / 256, 256>>>(Ch, Ctx);

    // ---- Wo GEMM: split-K=2, reduce with +x ----
    gemm_splitk<<<dim3(HID / 128, MROWS / 128, 2), 256, GEMM_SMEM_BYTES>>>(
        Ctx, Wor, QK, MROWS, HID, HID, HID / 2);
    reduce_res_k<<<(n4 + 255) / 256, 256>>>((const float4*)QK, (const float4*)x, (float4*)y);
    layernorm_rows_k<true><<<MROWS, 256>>>(y, g1, be1, x1);

    // ---- MLP ----
    gemm_tc<EPI_BIAS_GELU, true><<<dim3(MLPD / 128, MROWS / 128), 256, GEMM_SMEM_BYTES>>>(
        x1, W1r, Hf, b1, nullptr, MROWS, MLPD, HID);
    gemm_splitk<<<dim3(HID / 128, MROWS / 128, 2), 256, GEMM_SMEM_BYTES>>>(
        Hf, W2r, QK, MROWS, HID, MLPD, MLPD / 2);
    reduce_bias_res_k<<<(n4 + 255) / 256, 256>>>((const float4*)QK, b2, (const float4*)x1, (float4*)y2);
    layernorm_rows_k<false><<<MROWS, 256>>>(y2, g2, be2, out);
}

// round 10
// speedup vs baseline: 1.0141x; 1.0141x over previous
#include <cuda_runtime.h>
#include <math.h>
#include <stdint.h>

#define BATCH 8
#define LSEQ  1024
#define HID   768
#define NH    12
#define DH    64
#define MLPD  3072
#define MROWS (BATCH*LSEQ)    // 8192
#define NHEADS_TOT (BATCH*NH) // 96

// ---------------- static scratch ----------------
__device__ float g_QK [(size_t)MROWS*2*HID];   // QK output; later reused as split-K partials
__device__ float g_Qh [MROWS*HID];
__device__ float g_Kh [MROWS*HID];
__device__ float g_Ctx[MROWS*HID];
__device__ float g_x1 [MROWS*HID];
__device__ float g_Hf [(size_t)MROWS*MLPD];
__device__ float g_xr [MROWS*HID];
__device__ float g_Wqk[HID*2*HID];
__device__ float g_Wor[HID*HID];
__device__ float g_W1r[HID*MLPD];
__device__ float g_W2r[MLPD*HID];

// ---------------- helpers ----------------
__device__ __forceinline__ float gelu_f(float v) {
    return 0.5f * v * (1.0f + erff(v * 0.7071067811865475f));
}

__device__ __forceinline__ uint32_t f2tf32(float f) {
    uint32_t u;
    asm("cvt.rna.tf32.f32 %0, %1;" : "=r"(u) : "f"(f));
    return u;
}
__device__ __forceinline__ float rndtf(float f) { return __uint_as_float(f2tf32(f)); }

__device__ __forceinline__ void mma_tf32(float* d, const uint32_t* a, const uint32_t* b) {
    asm volatile(
        "mma.sync.aligned.m16n8k8.row.col.f32.tf32.tf32.f32 "
        "{%0,%1,%2,%3}, {%4,%5,%6,%7}, {%8,%9}, {%0,%1,%2,%3};\n"
        : "+f"(d[0]), "+f"(d[1]), "+f"(d[2]), "+f"(d[3])
        : "r"(a[0]), "r"(a[1]), "r"(a[2]), "r"(a[3]),
          "r"(b[0]), "r"(b[1]));
}

__device__ __forceinline__ void ldsm4(uint32_t* r, uint32_t addr) {
    asm volatile("ldmatrix.sync.aligned.m8n8.x4.shared.b16 {%0,%1,%2,%3}, [%4];"
        : "=r"(r[0]), "=r"(r[1]), "=r"(r[2]), "=r"(r[3]) : "r"(addr));
}

__device__ __forceinline__ void cp16(uint32_t dst, const void* src) {
    asm volatile("cp.async.cg.shared.global [%0], [%1], 16;\n" :: "r"(dst), "l"(src));
}
__device__ __forceinline__ void cp_commit() {
    asm volatile("cp.async.commit_group;\n");
}
template<int N>
__device__ __forceinline__ void cp_wait() {
    asm volatile("cp.async.wait_group %0;\n" :: "n"(N));
}

enum { EPI_NONE = 0, EPI_RES = 1, EPI_BIAS_GELU = 2, EPI_BIAS_RES = 3 };

// R8-proven config: BK=16, 4-stage cp.async pipeline
#define AS_STR 20
#define BS_STR 136
#define STAGES 4
#define GEMM_SMEM_BYTES (STAGES * (128 * AS_STR + 16 * BS_STR) * 4)

// ---------------- TF32 tensor-core GEMM: C = A(MxK) @ B(KxN) ----------------
template<int EPI, bool ROUND_OUT>
__global__ __launch_bounds__(256, 2) void gemm_tc(
    const float* __restrict__ A, const float* __restrict__ B, float* __restrict__ C,
    const float* __restrict__ bias, const float* __restrict__ res,
    int M, int N, int K)
{
    extern __shared__ uint32_t dynsmem[];
    uint32_t* As = dynsmem;
    uint32_t* Bs = dynsmem + STAGES * 128 * AS_STR;
    const uint32_t sA = (uint32_t)__cvta_generic_to_shared(As);
    const uint32_t sB = (uint32_t)__cvta_generic_to_shared(Bs);

    const int tid  = threadIdx.x;
    const int lane = tid & 31;
    const int warp = tid >> 5;
    const int grp  = lane >> 2;
    const int tg   = lane & 3;
    const int wm   = (warp >> 2) * 64;
    const int wn   = (warp & 3) * 32;
    const int bx   = blockIdx.x;
    const int by   = blockIdx.y;

    const int rl = lane & 15;
    const int cb = (lane >> 4) << 2;

    const int ar0 = tid >> 2,  ac0 = (tid & 3) * 4;
    const int ar1 = ar0 + 64;
    const int br0 = tid >> 5,  bc0 = (tid & 31) * 4;
    const int br1 = br0 + 8;

    const float* Abase = A + (size_t)(by * 128) * K;
    const float* Bbase = B + bx * 128;

    float acc[4][4][4];
    #pragma unroll
    for (int i = 0; i < 4; i++)
        #pragma unroll
        for (int j = 0; j < 4; j++)
            #pragma unroll
            for (int r = 0; r < 4; r++) acc[i][j][r] = 0.0f;

    const int ntiles = K >> 4;

    auto issue = [&](int t) {
        const int st = t & (STAGES - 1);
        const int k0 = t * 16;
        const uint32_t aoff = sA + (uint32_t)(st * 128 * AS_STR) * 4;
        const uint32_t boff = sB + (uint32_t)(st * 16 * BS_STR) * 4;
        cp16(aoff + (uint32_t)(ar0 * AS_STR + ac0) * 4, Abase + (size_t)ar0 * K + k0 + ac0);
        cp16(aoff + (uint32_t)(ar1 * AS_STR + ac0) * 4, Abase + (size_t)ar1 * K + k0 + ac0);
        cp16(boff + (uint32_t)(br0 * BS_STR + bc0) * 4, Bbase + (size_t)(k0 + br0) * N + bc0);
        cp16(boff + (uint32_t)(br1 * BS_STR + bc0) * 4, Bbase + (size_t)(k0 + br1) * N + bc0);
        cp_commit();
    };

    #pragma unroll
    for (int t = 0; t < STAGES - 1; t++) issue(t);

    for (int t = 0; t < ntiles; t++) {
        cp_wait<STAGES - 2>();
        __syncthreads();

        const int cur = t & (STAGES - 1);
        const uint32_t aBase = sA + (uint32_t)(cur * 128 * AS_STR) * 4;
        const uint32_t* Bc = Bs + cur * 16 * BS_STR;

        #pragma unroll
        for (int kk = 0; kk < 16; kk += 8) {
            uint32_t a[4][4], b[4][2];
            #pragma unroll
            for (int mt = 0; mt < 4; mt++)
                ldsm4(a[mt], aBase + (uint32_t)((wm + mt * 16 + rl) * AS_STR + kk + cb) * 4);
            #pragma unroll
            for (int nt = 0; nt < 4; nt++) {
                const int c = wn + nt * 8 + grp;
                b[nt][0] = Bc[(kk + tg) * BS_STR + c];
                b[nt][1] = Bc[(kk + tg + 4) * BS_STR + c];
            }
            #pragma unroll
            for (int mt = 0; mt < 4; mt++)
                #pragma unroll
                for (int nt = 0; nt < 4; nt++)
                    mma_tf32(acc[mt][nt], a[mt], b[nt]);
        }

        if (t + STAGES - 1 < ntiles) issue(t + STAGES - 1);
        else cp_commit();
    }

    #pragma unroll
    for (int mt = 0; mt < 4; mt++) {
        #pragma unroll
        for (int nt = 0; nt < 4; nt++) {
            const int r0 = by * 128 + wm + mt * 16 + grp;
            const int c0 = bx * 128 + wn + nt * 8 + tg * 2;
            float v0 = acc[mt][nt][0], v1 = acc[mt][nt][1];
            float v2 = acc[mt][nt][2], v3 = acc[mt][nt][3];
            if (EPI == EPI_RES) {
                const float2 r0v = *(const float2*)&res[(size_t)r0 * N + c0];
                const float2 r1v = *(const float2*)&res[(size_t)(r0 + 8) * N + c0];
                v0 += r0v.x; v1 += r0v.y; v2 += r1v.x; v3 += r1v.y;
            }
            if (EPI == EPI_BIAS_GELU) {
                const float2 bv = *(const float2*)&bias[c0];
                v0 = gelu_f(v0 + bv.x); v1 = gelu_f(v1 + bv.y);
                v2 = gelu_f(v2 + bv.x); v3 = gelu_f(v3 + bv.y);
            }
            if (EPI == EPI_BIAS_RES) {
                const float2 bv = *(const float2*)&bias[c0];
                const float2 r0v = *(const float2*)&res[(size_t)r0 * N + c0];
                const float2 r1v = *(const float2*)&res[(size_t)(r0 + 8) * N + c0];
                v0 += bv.x + r0v.x; v1 += bv.y + r0v.y;
                v2 += bv.x + r1v.x; v3 += bv.y + r1v.y;
            }
            if (ROUND_OUT) {
                v0 = rndtf(v0); v1 = rndtf(v1); v2 = rndtf(v2); v3 = rndtf(v3);
            }
            float2 w0 = {v0, v1}, w1 = {v2, v3};
            *(float2*)&C[(size_t)r0 * N + c0] = w0;
            *(float2*)&C[(size_t)(r0 + 8) * N + c0] = w1;
        }
    }
}

// ---------------- split-K=2 partial GEMM (R8 config) ----------------
__global__ __launch_bounds__(256, 2) void gemm_splitk(
    const float* __restrict__ A, const float* __restrict__ B, float* __restrict__ Cp,
    int M, int N, int lda, int Khalf)
{
    extern __shared__ uint32_t dynsmem[];
    uint32_t* As = dynsmem;
    uint32_t* Bs = dynsmem + STAGES * 128 * AS_STR;
    const uint32_t sA = (uint32_t)__cvta_generic_to_shared(As);
    const uint32_t sB = (uint32_t)__cvta_generic_to_shared(Bs);

    const int tid  = threadIdx.x;
    const int lane = tid & 31;
    const int warp = tid >> 5;
    const int grp  = lane >> 2;
    const int tg   = lane & 3;
    const int wm   = (warp >> 2) * 64;
    const int wn   = (warp & 3) * 32;
    const int bx   = blockIdx.x;
    const int by   = blockIdx.y;
    const int z    = blockIdx.z;

    const int rl = lane & 15;
    const int cb = (lane >> 4) << 2;

    const int ar0 = tid >> 2,  ac0 = (tid & 3) * 4;
    const int ar1 = ar0 + 64;
    const int br0 = tid >> 5,  bc0 = (tid & 31) * 4;
    const int br1 = br0 + 8;

    const float* Abase = A + (size_t)(by * 128) * lda + (size_t)z * Khalf;
    const float* Bbase = B + (size_t)z * Khalf * N + bx * 128;

    float acc[4][4][4];
    #pragma unroll
    for (int i = 0; i < 4; i++)
        #pragma unroll
        for (int j = 0; j < 4; j++)
            #pragma unroll
            for (int r = 0; r < 4; r++) acc[i][j][r] = 0.0f;

    const int ntiles = Khalf >> 4;

    auto issue = [&](int t) {
        const int st = t & (STAGES - 1);
        const int k0 = t * 16;
        const uint32_t aoff = sA + (uint32_t)(st * 128 * AS_STR) * 4;
        const uint32_t boff = sB + (uint32_t)(st * 16 * BS_STR) * 4;
        cp16(aoff + (uint32_t)(ar0 * AS_STR + ac0) * 4, Abase + (size_t)ar0 * lda + k0 + ac0);
        cp16(aoff + (uint32_t)(ar1 * AS_STR + ac0) * 4, Abase + (size_t)ar1 * lda + k0 + ac0);
        cp16(boff + (uint32_t)(br0 * BS_STR + bc0) * 4, Bbase + (size_t)(k0 + br0) * N + bc0);
        cp16(boff + (uint32_t)(br1 * BS_STR + bc0) * 4, Bbase + (size_t)(k0 + br1) * N + bc0);
        cp_commit();
    };

    #pragma unroll
    for (int t = 0; t < STAGES - 1; t++) issue(t);

    for (int t = 0; t < ntiles; t++) {
        cp_wait<STAGES - 2>();
        __syncthreads();

        const int cur = t & (STAGES - 1);
        const uint32_t aBase = sA + (uint32_t)(cur * 128 * AS_STR) * 4;
        const uint32_t* Bc = Bs + cur * 16 * BS_STR;

        #pragma unroll
        for (int kk = 0; kk < 16; kk += 8) {
            uint32_t a[4][4], b[4][2];
            #pragma unroll
            for (int mt = 0; mt < 4; mt++)
                ldsm4(a[mt], aBase + (uint32_t)((wm + mt * 16 + rl) * AS_STR + kk + cb) * 4);
            #pragma unroll
            for (int nt = 0; nt < 4; nt++) {
                const int c = wn + nt * 8 + grp;
                b[nt][0] = Bc[(kk + tg) * BS_STR + c];
                b[nt][1] = Bc[(kk + tg + 4) * BS_STR + c];
            }
            #pragma unroll
            for (int mt = 0; mt < 4; mt++)
                #pragma unroll
                for (int nt = 0; nt < 4; nt++)
                    mma_tf32(acc[mt][nt], a[mt], b[nt]);
        }

        if (t + STAGES - 1 < ntiles) issue(t + STAGES - 1);
        else cp_commit();
    }

    float* Cz = Cp + (size_t)z * M * N;
    #pragma unroll
    for (int mt = 0; mt < 4; mt++) {
        #pragma unroll
        for (int nt = 0; nt < 4; nt++) {
            const int r0 = by * 128 + wm + mt * 16 + grp;
            const int c0 = bx * 128 + wn + nt * 8 + tg * 2;
            float2 w0 = {acc[mt][nt][0], acc[mt][nt][1]};
            float2 w1 = {acc[mt][nt][2], acc[mt][nt][3]};
            *(float2*)&Cz[(size_t)r0 * N + c0] = w0;
            *(float2*)&Cz[(size_t)(r0 + 8) * N + c0] = w1;
        }
    }
}

// ---------------- fused split-K reduce + layernorm ----------------
// v[c] = p0[c] + p1[c] + res[c] (+ bias[c]); Y = LN(v) (optionally tf32-rounded)
template<bool RND, bool BIAS>
__global__ __launch_bounds__(256) void layernorm_fused_k(
    const float* __restrict__ p, const float* __restrict__ bias,
    const float* __restrict__ res, const float* __restrict__ g,
    const float* __restrict__ be, float* __restrict__ Y)
{
    const int row = blockIdx.x;
    const float* p0 = p + (size_t)row * HID;
    const float* p1 = p + (size_t)MROWS * HID + (size_t)row * HID;
    const float* r  = res + (size_t)row * HID;
    float* y = Y + (size_t)row * HID;
    const int tid = threadIdx.x;
    __shared__ float vbuf[HID];
    __shared__ float shs[8], shss[8];

    float s = 0.0f, ss = 0.0f;
    for (int c = tid; c < HID; c += 256) {
        float v = p0[c] + p1[c] + r[c];
        if (BIAS) v += bias[c];
        vbuf[c] = v;
        s += v;
        ss = fmaf(v, v, ss);
    }
    #pragma unroll
    for (int o = 16; o; o >>= 1) {
        s  += __shfl_xor_sync(0xffffffffu, s, o);
        ss += __shfl_xor_sync(0xffffffffu, ss, o);
    }
    if ((tid & 31) == 0) { shs[tid >> 5] = s; shss[tid >> 5] = ss; }
    __syncthreads();
    if (tid == 0) {
        float a = 0.0f, b = 0.0f;
        #pragma unroll
        for (int i = 0; i < 8; i++) { a += shs[i]; b += shss[i]; }
        shs[0] = a; shss[0] = b;
    }
    __syncthreads();
    const float mu  = shs[0]  * (1.0f / HID);
    const float var = shss[0] * (1.0f / HID) - mu * mu;
    const float inv = rsqrtf(var + 1e-5f);
    for (int c = tid; c < HID; c += 256) {
        float v = (vbuf[c] - mu) * inv * g[c] + be[c];
        y[c] = RND ? rndtf(v) : v;
    }
}

// ---------------- operand pre-rounding ----------------
#define NQK (HID*HID/4)
#define NWO (HID*HID/4)
#define NW1 (HID*MLPD/4)
#define NW2 (MLPD*HID/4)
#define NWB (NWO + NW1 + NW2)

__device__ __forceinline__ float4 rnd4(float4 v) {
    v.x = rndtf(v.x); v.y = rndtf(v.y); v.z = rndtf(v.z); v.w = rndtf(v.w);
    return v;
}

__global__ void round_wa_k(const float* __restrict__ Wq, const float* __restrict__ Wk) {
    int i = blockIdx.x * blockDim.x + threadIdx.x;
    if (i >= NQK) return;
    int k = i / (HID / 4), c = (i % (HID / 4)) * 4;
    *(float4*)(g_Wqk + (size_t)k * (2 * HID) + c)       = rnd4(*(const float4*)(Wq + (size_t)k * HID + c));
    *(float4*)(g_Wqk + (size_t)k * (2 * HID) + HID + c) = rnd4(*(const float4*)(Wk + (size_t)k * HID + c));
}

__global__ void round_wb_k(const float* __restrict__ Wo, const float* __restrict__ W1,
                           const float* __restrict__ W2) {
    int i = blockIdx.x * blockDim.x + threadIdx.x;
    if (i >= NWB) return;
    if (i < NWO) { ((float4*)g_Wor)[i] = rnd4(((const float4*)Wo)[i]); return; }
    i -= NWO;
    if (i < NW1) { ((float4*)g_W1r)[i] = rnd4(((const float4*)W1)[i]); return; }
    i -= NW1;
    ((float4*)g_W2r)[i] = rnd4(((const float4*)W2)[i]);
}

__global__ void round_x_k(const float4* __restrict__ in, float4* __restrict__ out, int n4) {
    int i = blockIdx.x * blockDim.x + threadIdx.x;
    if (i >= n4) return;
    out[i] = rnd4(in[i]);
}

// ---------------- permute to head-major ----------------
__global__ void to_head2_k(const float* __restrict__ QK,
                           float* __restrict__ Qh, float* __restrict__ Kh) {
    int idx = blockIdx.x * blockDim.x + threadIdx.x;
    if (idx >= MROWS * HID) return;
    int d = idx & 63;
    int l = (idx >> 6) & 1023;
    int z = idx >> 16;
    int n = z % NH, b = z / NH;
    const size_t src = (size_t)(b * LSEQ + l) * (2 * HID) + d * NH + n;
    Qh[idx] = QK[src];
    Kh[idx] = QK[src + HID];
}

// ---------------- fused flash attention (TF32 mma + LDSM) ----------------
// Epilogue writes DIRECTLY into interleaved Ctx layout (h = d*12 + n),
// tf32-rounded, eliminating the from_head permute kernel.
#define QS_STR 68
#define KS_STR 68
#define PS_STR 132
#define ATTN_SMEM_WORDS (128*QS_STR + 128*KS_STR + 128*PS_STR + 128 + 128 + 512 + 512)
#define ATTN_SMEM_BYTES (ATTN_SMEM_WORDS * 4)

__global__ __launch_bounds__(256) void attn_fused(
    const float* __restrict__ Qh, const float* __restrict__ Kh, float* __restrict__ Ctx)
{
    extern __shared__ uint32_t sm[];
    uint32_t* Qs = sm;
    uint32_t* Ks = Qs + 128 * QS_STR;
    uint32_t* Ps = Ks + 128 * KS_STR;
    float* Mrow  = (float*)(Ps + 128 * PS_STR);
    float* Srow  = Mrow + 128;
    float* red1  = Srow + 128;
    float* red2  = red1 + 512;

    const uint32_t qAddr = (uint32_t)__cvta_generic_to_shared(Qs);
    const uint32_t kAddr = (uint32_t)__cvta_generic_to_shared(Ks);
    const uint32_t pAddr = (uint32_t)__cvta_generic_to_shared(Ps);

    const int z   = blockIdx.y;
    const int l0  = blockIdx.x * 128;
    const int tid = threadIdx.x;
    const int lane = tid & 31;
    const int warp = tid >> 5;
    const int grp  = lane >> 2;
    const int tg   = lane & 3;
    const int wm   = (warp >> 2) * 64;
    const int wn   = (warp & 3) * 32;
    const int wn2  = (warp & 3) * 16;
    const int wc   = warp & 3;
    const int rl   = lane & 15;
    const int cbo  = (lane >> 4) << 2;

    const float* Qbase = Qh + ((size_t)z * LSEQ + l0) * DH;
    const float* Kbase = Kh + (size_t)z * LSEQ * DH;

    if (tid < 128) { Mrow[tid] = -3.0e38f; Srow[tid] = 0.0f; }

    #pragma unroll
    for (int i = 0; i < 8; i++) {
        int f = tid + 256 * i;
        int r = f >> 4, c = (f & 15) * 4;
        float4 q = *(const float4*)(Qbase + r * DH + c);
        Qs[r * QS_STR + c + 0] = f2tf32(0.125f * q.x);
        Qs[r * QS_STR + c + 1] = f2tf32(0.125f * q.y);
        Qs[r * QS_STR + c + 2] = f2tf32(0.125f * q.z);
        Qs[r * QS_STR + c + 3] = f2tf32(0.125f * q.w);
    }

    float acc_o[4][2][4];
    #pragma unroll
    for (int i = 0; i < 4; i++)
        #pragma unroll
        for (int j = 0; j < 2; j++)
            #pragma unroll
            for (int r = 0; r < 4; r++) acc_o[i][j][r] = 0.0f;

    __syncthreads();

    for (int mtile = 0; mtile < LSEQ / 128; mtile++) {
        const float* Kt = Kbase + (size_t)mtile * 128 * DH;
        #pragma unroll
        for (int i = 0; i < 8; i++) {
            int f = tid + 256 * i;
            int r = f >> 4, c = (f & 15) * 4;
            float4 k4 = *(const float4*)(Kt + r * DH + c);
            Ks[r * KS_STR + c + 0] = f2tf32(k4.x);
            Ks[r * KS_STR + c + 1] = f2tf32(k4.y);
            Ks[r * KS_STR + c + 2] = f2tf32(k4.z);
            Ks[r * KS_STR + c + 3] = f2tf32(k4.w);
        }
        __syncthreads();

        float s[4][4][4];
        #pragma unroll
        for (int i = 0; i < 4; i++)
            #pragma unroll
            for (int j = 0; j < 4; j++)
                #pragma unroll
                for (int r = 0; r < 4; r++) s[i][j][r] = 0.0f;

        #pragma unroll
        for (int kk = 0; kk < DH; kk += 8) {
            uint32_t a[4][4], b[4][2];
            #pragma unroll
            for (int mt = 0; mt < 4; mt++)
                ldsm4(a[mt], qAddr + (uint32_t)((wm + mt * 16 + rl) * QS_STR + kk + cbo) * 4);
            #pragma unroll
            for (int p = 0; p < 2; p++) {
                uint32_t t4[4];
                ldsm4(t4, kAddr + (uint32_t)((wn + p * 16 + rl) * KS_STR + kk + cbo) * 4);
                b[2 * p][0]     = t4[0];
                b[2 * p + 1][0] = t4[1];
                b[2 * p][1]     = t4[2];
                b[2 * p + 1][1] = t4[3];
            }
            #pragma unroll
            for (int mt = 0; mt < 4; mt++)
                #pragma unroll
                for (int nt = 0; nt < 4; nt++)
                    mma_tf32(s[mt][nt], a[mt], b[nt]);
        }

        #pragma unroll
        for (int mt = 0; mt < 4; mt++) {
            float mlo = -3.0e38f, mhi = -3.0e38f;
            #pragma unroll
            for (int nt = 0; nt < 4; nt++) {
                mlo = fmaxf(mlo, fmaxf(s[mt][nt][0], s[mt][nt][1]));
                mhi = fmaxf(mhi, fmaxf(s[mt][nt][2], s[mt][nt][3]));
            }
            mlo = fmaxf(mlo, __shfl_xor_sync(0xffffffffu, mlo, 1));
            mlo = fmaxf(mlo, __shfl_xor_sync(0xffffffffu, mlo, 2));
            mhi = fmaxf(mhi, __shfl_xor_sync(0xffffffffu, mhi, 1));
            mhi = fmaxf(mhi, __shfl_xor_sync(0xffffffffu, mhi, 2));
            if (tg == 0) {
                red1[(wm + mt * 16 + grp) * 4 + wc]     = mlo;
                red1[(wm + mt * 16 + grp + 8) * 4 + wc] = mhi;
            }
        }
        __syncthreads();

        float newlo[4], newhi[4], scllo[4], sclhi[4];
        #pragma unroll
        for (int mt = 0; mt < 4; mt++) {
            const int rlo = wm + mt * 16 + grp;
            const int rhi = rlo + 8;
            float4 v1 = *(const float4*)&red1[rlo * 4];
            float4 v2 = *(const float4*)&red1[rhi * 4];
            float tlo = fmaxf(fmaxf(v1.x, v1.y), fmaxf(v1.z, v1.w));
            float thi = fmaxf(fmaxf(v2.x, v2.y), fmaxf(v2.z, v2.w));
            float oldlo = Mrow[rlo], oldhi = Mrow[rhi];
            float nlo = fmaxf(oldlo, tlo), nhi = fmaxf(oldhi, thi);
            newlo[mt] = nlo; newhi[mt] = nhi;
            scllo[mt] = __expf(oldlo - nlo);
            sclhi[mt] = __expf(oldhi - nhi);

            float pslo = 0.0f, pshi = 0.0f;
            #pragma unroll
            for (int nt = 0; nt < 4; nt++) {
                const int c = wn + nt * 8 + 2 * tg;
                float p0 = __expf(s[mt][nt][0] - nlo);
                float p1 = __expf(s[mt][nt][1] - nlo);
                float p2 = __expf(s[mt][nt][2] - nhi);
                float p3 = __expf(s[mt][nt][3] - nhi);
                Ps[rlo * PS_STR + c]     = f2tf32(p0);
                Ps[rlo * PS_STR + c + 1] = f2tf32(p1);
                Ps[rhi * PS_STR + c]     = f2tf32(p2);
                Ps[rhi * PS_STR + c + 1] = f2tf32(p3);
                pslo += p0 + p1;
                pshi += p2 + p3;
            }
            pslo += __shfl_xor_sync(0xffffffffu, pslo, 1);
            pslo += __shfl_xor_sync(0xffffffffu, pslo, 2);
            pshi += __shfl_xor_sync(0xffffffffu, pshi, 1);
            pshi += __shfl_xor_sync(0xffffffffu, pshi, 2);
            if (tg == 0) {
                red2[rlo * 4 + wc] = pslo;
                red2[rhi * 4 + wc] = pshi;
            }
            #pragma unroll
            for (int nt2 = 0; nt2 < 2; nt2++) {
                acc_o[mt][nt2][0] *= scllo[mt];
                acc_o[mt][nt2][1] *= scllo[mt];
                acc_o[mt][nt2][2] *= sclhi[mt];
                acc_o[mt][nt2][3] *= sclhi[mt];
            }
        }
        __syncthreads();

        if (wc == 0 && tg == 0) {
            #pragma unroll
            for (int mt = 0; mt < 4; mt++) {
                const int rlo = wm + mt * 16 + grp;
                const int rhi = rlo + 8;
                float4 w1 = *(const float4*)&red2[rlo * 4];
                float4 w2 = *(const float4*)&red2[rhi * 4];
                Srow[rlo] = Srow[rlo] * scllo[mt] + (w1.x + w1.y + w1.z + w1.w);
                Srow[rhi] = Srow[rhi] * sclhi[mt] + (w2.x + w2.y + w2.z + w2.w);
                Mrow[rlo] = newlo[mt];
                Mrow[rhi] = newhi[mt];
            }
        }

        #pragma unroll
        for (int kk = 0; kk < 128; kk += 8) {
            uint32_t a[4][4], b[2][2];
            #pragma unroll
            for (int mt = 0; mt < 4; mt++)
                ldsm4(a[mt], pAddr + (uint32_t)((wm + mt * 16 + rl) * PS_STR + kk + cbo) * 4);
            #pragma unroll
            for (int nt2 = 0; nt2 < 2; nt2++) {
                const int c = wn2 + nt2 * 8 + grp;
                b[nt2][0] = Ks[(kk + tg) * KS_STR + c];
                b[nt2][1] = Ks[(kk + tg + 4) * KS_STR + c];
            }
            #pragma unroll
            for (int mt = 0; mt < 4; mt++)
                #pragma unroll
                for (int nt2 = 0; nt2 < 2; nt2++)
                    mma_tf32(acc_o[mt][nt2], a[mt], b[nt2]);
        }
        __syncthreads();
    }

    // ---- epilogue: normalize, round, scatter to interleaved Ctx ----
    // element (z = b*NH + n, l0 + r, d) -> Ctx[(b*LSEQ + l0 + r)*HID + d*NH + n]
    const int bq = z / NH;
    const int nh = z % NH;
    float* Cbase = Ctx + ((size_t)(bq * LSEQ + l0)) * HID + nh;
    #pragma unroll
    for (int mt = 0; mt < 4; mt++) {
        const int rlo = wm + mt * 16 + grp;
        const int rhi = rlo + 8;
        const float ilo = 1.0f / Srow[rlo];
        const float ihi = 1.0f / Srow[rhi];
        #pragma unroll
        for (int nt2 = 0; nt2 < 2; nt2++) {
            const int d0 = wn2 + nt2 * 8 + 2 * tg;
            float* plo = Cbase + (size_t)rlo * HID + d0 * NH;
            float* phi = Cbase + (size_t)rhi * HID + d0 * NH;
            plo[0]  = rndtf(acc_o[mt][nt2][0] * ilo);
            plo[NH] = rndtf(acc_o[mt][nt2][1] * ilo);
            phi[0]  = rndtf(acc_o[mt][nt2][2] * ihi);
            phi[NH] = rndtf(acc_o[mt][nt2][3] * ihi);
        }
    }
}

// ---------------- host launch ----------------
extern "C" void kernel_launch(void* const* d_in, const int* in_sizes, int n_in,
                              void* d_out, int out_size)
{
    const float* x   = (const float*)d_in[0];
    const float* Wq  = (const float*)d_in[1];
    const float* Wk  = (const float*)d_in[2];
    // d_in[3] = Wv: unused (ctx contracts with K in the reference)
    const float* Wo  = (const float*)d_in[4];
    const float* W1  = (const float*)d_in[5];
    const float* b1  = (const float*)d_in[6];
    const float* W2  = (const float*)d_in[7];
    const float* b2  = (const float*)d_in[8];
    const float* g1  = (const float*)d_in[9];
    const float* be1 = (const float*)d_in[10];
    const float* g2  = (const float*)d_in[11];
    const float* be2 = (const float*)d_in[12];
    float* out = (float*)d_out;

    float *QK, *Qh, *Kh, *Ctx, *x1, *Hf;
    float *xr, *Wqk, *Wor, *W1r, *W2r;
    cudaGetSymbolAddress((void**)&QK, g_QK);
    cudaGetSymbolAddress((void**)&Qh, g_Qh);
    cudaGetSymbolAddress((void**)&Kh, g_Kh);
    cudaGetSymbolAddress((void**)&Ctx,g_Ctx);
    cudaGetSymbolAddress((void**)&x1, g_x1);
    cudaGetSymbolAddress((void**)&Hf, g_Hf);
    cudaGetSymbolAddress((void**)&xr, g_xr);
    cudaGetSymbolAddress((void**)&Wqk,g_Wqk);
    cudaGetSymbolAddress((void**)&Wor,g_Wor);
    cudaGetSymbolAddress((void**)&W1r,g_W1r);
    cudaGetSymbolAddress((void**)&W2r,g_W2r);

    static bool attrs_set = false;
    if (!attrs_set) {
        cudaFuncSetAttribute(attn_fused, cudaFuncAttributeMaxDynamicSharedMemorySize, ATTN_SMEM_BYTES);
        cudaFuncSetAttribute(gemm_tc<EPI_NONE, false>,      cudaFuncAttributeMaxDynamicSharedMemorySize, GEMM_SMEM_BYTES);
        cudaFuncSetAttribute(gemm_tc<EPI_BIAS_GELU, true>,  cudaFuncAttributeMaxDynamicSharedMemorySize, GEMM_SMEM_BYTES);
        cudaFuncSetAttribute(gemm_splitk,                   cudaFuncAttributeMaxDynamicSharedMemorySize, GEMM_SMEM_BYTES);
        attrs_set = true;
    }

    const int nperm = MROWS * HID;
    const int n4 = MROWS * HID / 4;

    // ---- operand pre-rounding (RNA->tf32) ----
    round_wa_k<<<(NQK + 255) / 256, 256>>>(Wq, Wk);
    round_wb_k<<<(NWB + 255) / 256, 256>>>(Wo, W1, W2);
    round_x_k<<<(n4 + 255) / 256, 256>>>((const float4*)x, (float4*)xr, n4);

    // ---- QK merged GEMM ----
    gemm_tc<EPI_NONE, false><<<dim3(2 * HID / 128, MROWS / 128), 256, GEMM_SMEM_BYTES>>>(
        xr, Wqk, QK, nullptr, nullptr, MROWS, 2 * HID, HID);

    to_head2_k<<<(nperm + 255) / 256, 256>>>(QK, Qh, Kh);

    // ---- fused flash attention: writes tf32-rounded interleaved Ctx directly ----
    attn_fused<<<dim3(LSEQ / 128, NHEADS_TOT), 256, ATTN_SMEM_BYTES>>>(Qh, Kh, Ctx);

    // ---- Wo GEMM: split-K=2 partials -> fused reduce(+x) + LN (tf32-rounded x1) ----
    gemm_splitk<<<dim3(HID / 128, MROWS / 128, 2), 256, GEMM_SMEM_BYTES>>>(
        Ctx, Wor, QK, MROWS, HID, HID, HID / 2);
    layernorm_fused_k<true, false><<<MROWS, 256>>>(QK, nullptr, x, g1, be1, x1);

    // ---- MLP ----
    gemm_tc<EPI_BIAS_GELU, true><<<dim3(MLPD / 128, MROWS / 128), 256, GEMM_SMEM_BYTES>>>(
        x1, W1r, Hf, b1, nullptr, MROWS, MLPD, HID);
    gemm_splitk<<<dim3(HID / 128, MROWS / 128, 2), 256, GEMM_SMEM_BYTES>>>(
        Hf, W2r, QK, MROWS, HID, MLPD, MLPD / 2);
    layernorm_fused_k<false, true><<<MROWS, 256>>>(QK, b2, x1, g2, be2, out);
}

// round 12
// speedup vs baseline: 1.3492x; 1.3303x over previous
#include <cuda_runtime.h>
#include <cuda_fp16.h>
#include <math.h>
#include <stdint.h>

#define BATCH 8
#define LSEQ  1024
#define HID   768
#define NH    12
#define DH    64
#define MLPD  3072
#define MROWS (BATCH*LSEQ)    // 8192
#define NHEADS_TOT (BATCH*NH) // 96

// ---------------- static scratch ----------------
__device__ float  g_QK [(size_t)MROWS*2*HID];  // QK output; later split-K partials
__device__ float  g_Qh [MROWS*HID];
__device__ float  g_Kh [MROWS*HID];
__device__ float  g_x1f[MROWS*HID];
__device__ __half g_xh  [MROWS*HID];
__device__ __half g_Ctxh[MROWS*HID];
__device__ __half g_x1h [MROWS*HID];
__device__ __half g_Hfh [(size_t)MROWS*MLPD];
__device__ __half g_Wqkh[(size_t)2*HID*HID];   // [1536][768] N-major
__device__ __half g_Worh[HID*HID];             // [768][768]
__device__ __half g_W1h [(size_t)MLPD*HID];    // [3072][768]
__device__ __half g_W2h [(size_t)HID*MLPD];    // [768][3072]

// ---------------- helpers ----------------
__device__ __forceinline__ float gelu_f(float v) {
    return 0.5f * v * (1.0f + erff(v * 0.7071067811865475f));
}

__device__ __forceinline__ uint32_t f2tf32(float f) {
    uint32_t u;
    asm("cvt.rna.tf32.f32 %0, %1;" : "=r"(u) : "f"(f));
    return u;
}

__device__ __forceinline__ void mma_tf32(float* d, const uint32_t* a, const uint32_t* b) {
    asm volatile(
        "mma.sync.aligned.m16n8k8.row.col.f32.tf32.tf32.f32 "
        "{%0,%1,%2,%3}, {%4,%5,%6,%7}, {%8,%9}, {%0,%1,%2,%3};\n"
        : "+f"(d[0]), "+f"(d[1]), "+f"(d[2]), "+f"(d[3])
        : "r"(a[0]), "r"(a[1]), "r"(a[2]), "r"(a[3]),
          "r"(b[0]), "r"(b[1]));
}

__device__ __forceinline__ void mma_f16(float* d, const uint32_t* a, const uint32_t* b) {
    asm volatile(
        "mma.sync.aligned.m16n8k16.row.col.f32.f16.f16.f32 "
        "{%0,%1,%2,%3}, {%4,%5,%6,%7}, {%8,%9}, {%0,%1,%2,%3};\n"
        : "+f"(d[0]), "+f"(d[1]), "+f"(d[2]), "+f"(d[3])
        : "r"(a[0]), "r"(a[1]), "r"(a[2]), "r"(a[3]),
          "r"(b[0]), "r"(b[1]));
}

__device__ __forceinline__ void ldsm4(uint32_t* r, uint32_t addr) {
    asm volatile("ldmatrix.sync.aligned.m8n8.x4.shared.b16 {%0,%1,%2,%3}, [%4];"
        : "=r"(r[0]), "=r"(r[1]), "=r"(r[2]), "=r"(r[3]) : "r"(addr));
}

__device__ __forceinline__ void cp16(uint32_t dst, const void* src) {
    asm volatile("cp.async.cg.shared.global [%0], [%1], 16;\n" :: "r"(dst), "l"(src));
}
__device__ __forceinline__ void cp_commit() {
    asm volatile("cp.async.commit_group;\n");
}
template<int N>
__device__ __forceinline__ void cp_wait() {
    asm volatile("cp.async.wait_group %0;\n" :: "n"(N));
}

enum { EPI_NONE = 0, EPI_BIAS_GELU = 2 };

// ---------------- FP16 tensor-core GEMM: C = A(MxK) @ Bt(NxK)^T ----------------
// A row-major [M][K] half, Bt [N][K] half. 128x128 CTA tile, BK=32,
// 4-stage cp.async pipeline. Fragments via ldmatrix (A non-trans, B via [N][K]).
#define HS_STR 40    // halves per smem row (32 data + 8 pad); 80B, conflict-free
#define STAGES 4
#define TILE_HALVES (128 * HS_STR)
#define TILE_BYTES  (TILE_HALVES * 2)
#define GEMM_SMEM_BYTES (STAGES * 2 * TILE_BYTES)

// fragment loads shared by both GEMM kernels
#define GEMM_CORE_LOOP(aBase, bBase) \
    _Pragma("unroll") \
    for (int kk = 0; kk < 32; kk += 16) { \
        uint32_t a[4][4], b[4][2]; \
        _Pragma("unroll") \
        for (int mt = 0; mt < 4; mt++) \
            ldsm4(a[mt], (aBase) + (uint32_t)((wm + mt * 16 + rl16) * HS_STR + kk + ko8) * 2); \
        _Pragma("unroll") \
        for (int nb = 0; nb < 2; nb++) { \
            uint32_t t4[4]; \
            ldsm4(t4, (bBase) + (uint32_t)((wn + nb * 16 + brow) * HS_STR + kk + bko) * 2); \
            b[2 * nb][0]     = t4[0]; \
            b[2 * nb][1]     = t4[1]; \
            b[2 * nb + 1][0] = t4[2]; \
            b[2 * nb + 1][1] = t4[3]; \
        } \
        _Pragma("unroll") \
        for (int mt = 0; mt < 4; mt++) \
            _Pragma("unroll") \
            for (int nt = 0; nt < 4; nt++) \
                mma_f16(acc[mt][nt], a[mt], b[nt]); \
    }

template<int EPI, bool OUTH>
__global__ __launch_bounds__(256, 2) void gemm_h(
    const __half* __restrict__ A, const __half* __restrict__ Bt, void* __restrict__ Cv,
    const float* __restrict__ bias, int M, int N, int K)
{
    extern __shared__ __half hsm[];
    const uint32_t sA = (uint32_t)__cvta_generic_to_shared(hsm);
    const uint32_t sB = sA + STAGES * TILE_BYTES;

    const int tid  = threadIdx.x;
    const int lane = tid & 31;
    const int warp = tid >> 5;
    const int grp  = lane >> 2;
    const int tg   = lane & 3;
    const int wm   = (warp >> 2) * 64;
    const int wn   = (warp & 3) * 32;
    const int bx   = blockIdx.x;
    const int by   = blockIdx.y;

    const int rl16 = lane & 15;
    const int ko8  = (lane >> 4) << 3;
    const int brow = (lane & 7) + ((lane >> 4) << 3);
    const int bko  = ((lane >> 3) & 1) << 3;

    const __half* Abase = A  + (size_t)(by * 128) * K;
    const __half* Bbase = Bt + (size_t)(bx * 128) * K;

    float acc[4][4][4];
    #pragma unroll
    for (int i = 0; i < 4; i++)
        #pragma unroll
        for (int j = 0; j < 4; j++)
            #pragma unroll
            for (int r = 0; r < 4; r++) acc[i][j][r] = 0.0f;

    const int nt_ = K >> 5;

    auto issue = [&](int t) {
        const int st = t & (STAGES - 1);
        const int k0 = t << 5;
        const uint32_t aoff = sA + st * TILE_BYTES;
        const uint32_t boff = sB + st * TILE_BYTES;
        #pragma unroll
        for (int i = 0; i < 2; i++) {
            const int c = tid + 256 * i;
            const int r = c >> 2, ch = (c & 3) * 8;
            cp16(aoff + (uint32_t)(r * HS_STR + ch) * 2, Abase + (size_t)r * K + k0 + ch);
            cp16(boff + (uint32_t)(r * HS_STR + ch) * 2, Bbase + (size_t)r * K + k0 + ch);
        }
        cp_commit();
    };

    #pragma unroll
    for (int t = 0; t < STAGES - 1; t++) issue(t);

    for (int t = 0; t < nt_; t++) {
        cp_wait<STAGES - 2>();
        __syncthreads();
        const int cur = t & (STAGES - 1);
        const uint32_t aBase = sA + cur * TILE_BYTES;
        const uint32_t bBase = sB + cur * TILE_BYTES;
        GEMM_CORE_LOOP(aBase, bBase)
        if (t + STAGES - 1 < nt_) issue(t + STAGES - 1);
        else cp_commit();
    }

    #pragma unroll
    for (int mt = 0; mt < 4; mt++) {
        #pragma unroll
        for (int nt = 0; nt < 4; nt++) {
            const int r0 = by * 128 + wm + mt * 16 + grp;
            const int c0 = bx * 128 + wn + nt * 8 + tg * 2;
            float v0 = acc[mt][nt][0], v1 = acc[mt][nt][1];
            float v2 = acc[mt][nt][2], v3 = acc[mt][nt][3];
            if (EPI == EPI_BIAS_GELU) {
                const float2 bv = *(const float2*)&bias[c0];
                v0 = gelu_f(v0 + bv.x); v1 = gelu_f(v1 + bv.y);
                v2 = gelu_f(v2 + bv.x); v3 = gelu_f(v3 + bv.y);
            }
            if (OUTH) {
                __half* Ch = (__half*)Cv;
                *(__half2*)&Ch[(size_t)r0 * N + c0] =
                    __floats2half2_rn(v0, v1);
                *(__half2*)&Ch[(size_t)(r0 + 8) * N + c0] =
                    __floats2half2_rn(v2, v3);
            } else {
                float* Cf = (float*)Cv;
                float2 w0 = {v0, v1}, w1 = {v2, v3};
                *(float2*)&Cf[(size_t)r0 * N + c0] = w0;
                *(float2*)&Cf[(size_t)(r0 + 8) * N + c0] = w1;
            }
        }
    }
}

// ---------------- FP16 split-K=2 partial GEMM ----------------
__global__ __launch_bounds__(256, 2) void gemm_h_splitk(
    const __half* __restrict__ A, const __half* __restrict__ Bt, float* __restrict__ Cp,
    int M, int N, int ldk, int Khalf)
{
    extern __shared__ __half hsm[];
    const uint32_t sA = (uint32_t)__cvta_generic_to_shared(hsm);
    const uint32_t sB = sA + STAGES * TILE_BYTES;

    const int tid  = threadIdx.x;
    const int lane = tid & 31;
    const int warp = tid >> 5;
    const int grp  = lane >> 2;
    const int tg   = lane & 3;
    const int wm   = (warp >> 2) * 64;
    const int wn   = (warp & 3) * 32;
    const int bx   = blockIdx.x;
    const int by   = blockIdx.y;
    const int z    = blockIdx.z;

    const int rl16 = lane & 15;
    const int ko8  = (lane >> 4) << 3;
    const int brow = (lane & 7) + ((lane >> 4) << 3);
    const int bko  = ((lane >> 3) & 1) << 3;

    const __half* Abase = A  + (size_t)(by * 128) * ldk + (size_t)z * Khalf;
    const __half* Bbase = Bt + (size_t)(bx * 128) * ldk + (size_t)z * Khalf;

    float acc[4][4][4];
    #pragma unroll
    for (int i = 0; i < 4; i++)
        #pragma unroll
        for (int j = 0; j < 4; j++)
            #pragma unroll
            for (int r = 0; r < 4; r++) acc[i][j][r] = 0.0f;

    const int nt_ = Khalf >> 5;

    auto issue = [&](int t) {
        const int st = t & (STAGES - 1);
        const int k0 = t << 5;
        const uint32_t aoff = sA + st * TILE_BYTES;
        const uint32_t boff = sB + st * TILE_BYTES;
        #pragma unroll
        for (int i = 0; i < 2; i++) {
            const int c = tid + 256 * i;
            const int r = c >> 2, ch = (c & 3) * 8;
            cp16(aoff + (uint32_t)(r * HS_STR + ch) * 2, Abase + (size_t)r * ldk + k0 + ch);
            cp16(boff + (uint32_t)(r * HS_STR + ch) * 2, Bbase + (size_t)r * ldk + k0 + ch);
        }
        cp_commit();
    };

    #pragma unroll
    for (int t = 0; t < STAGES - 1; t++) issue(t);

    for (int t = 0; t < nt_; t++) {
        cp_wait<STAGES - 2>();
        __syncthreads();
        const int cur = t & (STAGES - 1);
        const uint32_t aBase = sA + cur * TILE_BYTES;
        const uint32_t bBase = sB + cur * TILE_BYTES;
        GEMM_CORE_LOOP(aBase, bBase)
        if (t + STAGES - 1 < nt_) issue(t + STAGES - 1);
        else cp_commit();
    }

    float* Cz = Cp + (size_t)z * M * N;
    #pragma unroll
    for (int mt = 0; mt < 4; mt++) {
        #pragma unroll
        for (int nt = 0; nt < 4; nt++) {
            const int r0 = by * 128 + wm + mt * 16 + grp;
            const int c0 = bx * 128 + wn + nt * 8 + tg * 2;
            float2 w0 = {acc[mt][nt][0], acc[mt][nt][1]};
            float2 w1 = {acc[mt][nt][2], acc[mt][nt][3]};
            *(float2*)&Cz[(size_t)r0 * N + c0] = w0;
            *(float2*)&Cz[(size_t)(r0 + 8) * N + c0] = w1;
        }
    }
}

// ---------------- fused split-K reduce + layernorm ----------------
// v = p0 + p1 + res (+bias); Yf = LN(v); optionally Yh = half(LN(v))
template<bool BIAS, bool HOUT>
__global__ __launch_bounds__(256) void layernorm_fused_k(
    const float* __restrict__ p, const float* __restrict__ bias,
    const float* __restrict__ res, const float* __restrict__ g,
    const float* __restrict__ be, float* __restrict__ Yf, __half* __restrict__ Yh)
{
    const int row = blockIdx.x;
    const float* p0 = p + (size_t)row * HID;
    const float* p1 = p + (size_t)MROWS * HID + (size_t)row * HID;
    const float* r  = res + (size_t)row * HID;
    const int tid = threadIdx.x;
    __shared__ float vbuf[HID];
    __shared__ float shs[8], shss[8];

    float s = 0.0f, ss = 0.0f;
    for (int c = tid; c < HID; c += 256) {
        float v = p0[c] + p1[c] + r[c];
        if (BIAS) v += bias[c];
        vbuf[c] = v;
        s += v;
        ss = fmaf(v, v, ss);
    }
    #pragma unroll
    for (int o = 16; o; o >>= 1) {
        s  += __shfl_xor_sync(0xffffffffu, s, o);
        ss += __shfl_xor_sync(0xffffffffu, ss, o);
    }
    if ((tid & 31) == 0) { shs[tid >> 5] = s; shss[tid >> 5] = ss; }
    __syncthreads();
    if (tid == 0) {
        float a = 0.0f, b = 0.0f;
        #pragma unroll
        for (int i = 0; i < 8; i++) { a += shs[i]; b += shss[i]; }
        shs[0] = a; shss[0] = b;
    }
    __syncthreads();
    const float mu  = shs[0]  * (1.0f / HID);
    const float var = shss[0] * (1.0f / HID) - mu * mu;
    const float inv = rsqrtf(var + 1e-5f);
    for (int c = tid; c < HID; c += 256) {
        float v = (vbuf[c] - mu) * inv * g[c] + be[c];
        Yf[(size_t)row * HID + c] = v;
        if (HOUT) Yh[(size_t)row * HID + c] = __float2half_rn(v);
    }
}

// ---------------- operand conversion ----------------
// transpose + fp16: Wt[n][k] = half(W[k][n])
__global__ void transpose_h_k(const float* __restrict__ W, __half* __restrict__ Wt,
                              int K, int N) {
    __shared__ float tb[32][33];
    const int n0 = blockIdx.x * 32;
    const int k0 = blockIdx.y * 32;
    const int tx = threadIdx.x, ty = threadIdx.y;
    #pragma unroll
    for (int j = ty; j < 32; j += 8)
        tb[j][tx] = W[(size_t)(k0 + j) * N + n0 + tx];
    __syncthreads();
    #pragma unroll
    for (int j = ty; j < 32; j += 8)
        Wt[(size_t)(n0 + j) * K + k0 + tx] = __float2half_rn(tb[tx][j]);
}

__global__ void tohalf_k(const float4* __restrict__ in, __half2* __restrict__ out, int n4) {
    int i = blockIdx.x * blockDim.x + threadIdx.x;
    if (i >= n4) return;
    float4 v = in[i];
    out[2 * i]     = __floats2half2_rn(v.x, v.y);
    out[2 * i + 1] = __floats2half2_rn(v.z, v.w);
}

// ---------------- permute to head-major ----------------
__global__ void to_head2_k(const float* __restrict__ QK,
                           float* __restrict__ Qh, float* __restrict__ Kh) {
    int idx = blockIdx.x * blockDim.x + threadIdx.x;
    if (idx >= MROWS * HID) return;
    int d = idx & 63;
    int l = (idx >> 6) & 1023;
    int z = idx >> 16;
    int n = z % NH, b = z / NH;
    const size_t src = (size_t)(b * LSEQ + l) * (2 * HID) + d * NH + n;
    Qh[idx] = QK[src];
    Kh[idx] = QK[src + HID];
}

// ---------------- fused flash attention (TF32 mma + LDSM) ----------------
// Epilogue writes fp16 into interleaved Ctx layout (h = d*12 + n).
#define QS_STR 68
#define KS_STR 68
#define PS_STR 132
#define ATTN_SMEM_WORDS (128*QS_STR + 128*KS_STR + 128*PS_STR + 128 + 128 + 512 + 512)
#define ATTN_SMEM_BYTES (ATTN_SMEM_WORDS * 4)

__global__ __launch_bounds__(256) void attn_fused(
    const float* __restrict__ Qh, const float* __restrict__ Kh, __half* __restrict__ Ctx)
{
    extern __shared__ uint32_t sm[];
    uint32_t* Qs = sm;
    uint32_t* Ks = Qs + 128 * QS_STR;
    uint32_t* Ps = Ks + 128 * KS_STR;
    float* Mrow  = (float*)(Ps + 128 * PS_STR);
    float* Srow  = Mrow + 128;
    float* red1  = Srow + 128;
    float* red2  = red1 + 512;

    const uint32_t qAddr = (uint32_t)__cvta_generic_to_shared(Qs);
    const uint32_t kAddr = (uint32_t)__cvta_generic_to_shared(Ks);
    const uint32_t pAddr = (uint32_t)__cvta_generic_to_shared(Ps);

    const int z   = blockIdx.y;
    const int l0  = blockIdx.x * 128;
    const int tid = threadIdx.x;
    const int lane = tid & 31;
    const int warp = tid >> 5;
    const int grp  = lane >> 2;
    const int tg   = lane & 3;
    const int wm   = (warp >> 2) * 64;
    const int wn   = (warp & 3) * 32;
    const int wn2  = (warp & 3) * 16;
    const int wc   = warp & 3;
    const int rl   = lane & 15;
    const int cbo  = (lane >> 4) << 2;

    const float* Qbase = Qh + ((size_t)z * LSEQ + l0) * DH;
    const float* Kbase = Kh + (size_t)z * LSEQ * DH;

    if (tid < 128) { Mrow[tid] = -3.0e38f; Srow[tid] = 0.0f; }

    #pragma unroll
    for (int i = 0; i < 8; i++) {
        int f = tid + 256 * i;
        int r = f >> 4, c = (f & 15) * 4;
        float4 q = *(const float4*)(Qbase + r * DH + c);
        Qs[r * QS_STR + c + 0] = f2tf32(0.125f * q.x);
        Qs[r * QS_STR + c + 1] = f2tf32(0.125f * q.y);
        Qs[r * QS_STR + c + 2] = f2tf32(0.125f * q.z);
        Qs[r * QS_STR + c + 3] = f2tf32(0.125f * q.w);
    }

    float acc_o[4][2][4];
    #pragma unroll
    for (int i = 0; i < 4; i++)
        #pragma unroll
        for (int j = 0; j < 2; j++)
            #pragma unroll
            for (int r = 0; r < 4; r++) acc_o[i][j][r] = 0.0f;

    __syncthreads();

    for (int mtile = 0; mtile < LSEQ / 128; mtile++) {
        const float* Kt = Kbase + (size_t)mtile * 128 * DH;
        #pragma unroll
        for (int i = 0; i < 8; i++) {
            int f = tid + 256 * i;
            int r = f >> 4, c = (f & 15) * 4;
            float4 k4 = *(const float4*)(Kt + r * DH + c);
            Ks[r * KS_STR + c + 0] = f2tf32(k4.x);
            Ks[r * KS_STR + c + 1] = f2tf32(k4.y);
            Ks[r * KS_STR + c + 2] = f2tf32(k4.z);
            Ks[r * KS_STR + c + 3] = f2tf32(k4.w);
        }
        __syncthreads();

        float s[4][4][4];
        #pragma unroll
        for (int i = 0; i < 4; i++)
            #pragma unroll
            for (int j = 0; j < 4; j++)
                #pragma unroll
                for (int r = 0; r < 4; r++) s[i][j][r] = 0.0f;

        #pragma unroll
        for (int kk = 0; kk < DH; kk += 8) {
            uint32_t a[4][4], b[4][2];
            #pragma unroll
            for (int mt = 0; mt < 4; mt++)
                ldsm4(a[mt], qAddr + (uint32_t)((wm + mt * 16 + rl) * QS_STR + kk + cbo) * 4);
            #pragma unroll
            for (int p = 0; p < 2; p++) {
                uint32_t t4[4];
                ldsm4(t4, kAddr + (uint32_t)((wn + p * 16 + rl) * KS_STR + kk + cbo) * 4);
                b[2 * p][0]     = t4[0];
                b[2 * p + 1][0] = t4[1];
                b[2 * p][1]     = t4[2];
                b[2 * p + 1][1] = t4[3];
            }
            #pragma unroll
            for (int mt = 0; mt < 4; mt++)
                #pragma unroll
                for (int nt = 0; nt < 4; nt++)
                    mma_tf32(s[mt][nt], a[mt], b[nt]);
        }

        #pragma unroll
        for (int mt = 0; mt < 4; mt++) {
            float mlo = -3.0e38f, mhi = -3.0e38f;
            #pragma unroll
            for (int nt = 0; nt < 4; nt++) {
                mlo = fmaxf(mlo, fmaxf(s[mt][nt][0], s[mt][nt][1]));
                mhi = fmaxf(mhi, fmaxf(s[mt][nt][2], s[mt][nt][3]));
            }
            mlo = fmaxf(mlo, __shfl_xor_sync(0xffffffffu, mlo, 1));
            mlo = fmaxf(mlo, __shfl_xor_sync(0xffffffffu, mlo, 2));
            mhi = fmaxf(mhi, __shfl_xor_sync(0xffffffffu, mhi, 1));
            mhi = fmaxf(mhi, __shfl_xor_sync(0xffffffffu, mhi, 2));
            if (tg == 0) {
                red1[(wm + mt * 16 + grp) * 4 + wc]     = mlo;
                red1[(wm + mt * 16 + grp + 8) * 4 + wc] = mhi;
            }
        }
        __syncthreads();

        float newlo[4], newhi[4], scllo[4], sclhi[4];
        #pragma unroll
        for (int mt = 0; mt < 4; mt++) {
            const int rlo = wm + mt * 16 + grp;
            const int rhi = rlo + 8;
            float4 v1 = *(const float4*)&red1[rlo * 4];
            float4 v2 = *(const float4*)&red1[rhi * 4];
            float tlo = fmaxf(fmaxf(v1.x, v1.y), fmaxf(v1.z, v1.w));
            float thi = fmaxf(fmaxf(v2.x, v2.y), fmaxf(v2.z, v2.w));
            float oldlo = Mrow[rlo], oldhi = Mrow[rhi];
            float nlo = fmaxf(oldlo, tlo), nhi = fmaxf(oldhi, thi);
            newlo[mt] = nlo; newhi[mt] = nhi;
            scllo[mt] = __expf(oldlo - nlo);
            sclhi[mt] = __expf(oldhi - nhi);

            float pslo = 0.0f, pshi = 0.0f;
            #pragma unroll
            for (int nt = 0; nt < 4; nt++) {
                const int c = wn + nt * 8 + 2 * tg;
                float p0 = __expf(s[mt][nt][0] - nlo);
                float p1 = __expf(s[mt][nt][1] - nlo);
                float p2 = __expf(s[mt][nt][2] - nhi);
                float p3 = __expf(s[mt][nt][3] - nhi);
                Ps[rlo * PS_STR + c]     = f2tf32(p0);
                Ps[rlo * PS_STR + c + 1] = f2tf32(p1);
                Ps[rhi * PS_STR + c]     = f2tf32(p2);
                Ps[rhi * PS_STR + c + 1] = f2tf32(p3);
                pslo += p0 + p1;
                pshi += p2 + p3;
            }
            pslo += __shfl_xor_sync(0xffffffffu, pslo, 1);
            pslo += __shfl_xor_sync(0xffffffffu, pslo, 2);
            pshi += __shfl_xor_sync(0xffffffffu, pshi, 1);
            pshi += __shfl_xor_sync(0xffffffffu, pshi, 2);
            if (tg == 0) {
                red2[rlo * 4 + wc] = pslo;
                red2[rhi * 4 + wc] = pshi;
            }
            #pragma unroll
            for (int nt2 = 0; nt2 < 2; nt2++) {
                acc_o[mt][nt2][0] *= scllo[mt];
                acc_o[mt][nt2][1] *= scllo[mt];
                acc_o[mt][nt2][2] *= sclhi[mt];
                acc_o[mt][nt2][3] *= sclhi[mt];
            }
        }
        __syncthreads();

        if (wc == 0 && tg == 0) {
            #pragma unroll
            for (int mt = 0; mt < 4; mt++) {
                const int rlo = wm + mt * 16 + grp;
                const int rhi = rlo + 8;
                float4 w1 = *(const float4*)&red2[rlo * 4];
                float4 w2 = *(const float4*)&red2[rhi * 4];
                Srow[rlo] = Srow[rlo] * scllo[mt] + (w1.x + w1.y + w1.z + w1.w);
                Srow[rhi] = Srow[rhi] * sclhi[mt] + (w2.x + w2.y + w2.z + w2.w);
                Mrow[rlo] = newlo[mt];
                Mrow[rhi] = newhi[mt];
            }
        }

        #pragma unroll
        for (int kk = 0; kk < 128; kk += 8) {
            uint32_t a[4][4], b[2][2];
            #pragma unroll
            for (int mt = 0; mt < 4; mt++)
                ldsm4(a[mt], pAddr + (uint32_t)((wm + mt * 16 + rl) * PS_STR + kk + cbo) * 4);
            #pragma unroll
            for (int nt2 = 0; nt2 < 2; nt2++) {
                const int c = wn2 + nt2 * 8 + grp;
                b[nt2][0] = Ks[(kk + tg) * KS_STR + c];
                b[nt2][1] = Ks[(kk + tg + 4) * KS_STR + c];
            }
            #pragma unroll
            for (int mt = 0; mt < 4; mt++)
                #pragma unroll
                for (int nt2 = 0; nt2 < 2; nt2++)
                    mma_tf32(acc_o[mt][nt2], a[mt], b[nt2]);
        }
        __syncthreads();
    }

    // epilogue: normalize, fp16-round, scatter to interleaved Ctx (h = d*12 + n)
    const int bq = z / NH;
    const int nh = z % NH;
    __half* Cbase = Ctx + ((size_t)(bq * LSEQ + l0)) * HID + nh;
    #pragma unroll
    for (int mt = 0; mt < 4; mt++) {
        const int rlo = wm + mt * 16 + grp;
        const int rhi = rlo + 8;
        const float ilo = 1.0f / Srow[rlo];
        const float ihi = 1.0f / Srow[rhi];
        #pragma unroll
        for (int nt2 = 0; nt2 < 2; nt2++) {
            const int d0 = wn2 + nt2 * 8 + 2 * tg;
            __half* plo = Cbase + (size_t)rlo * HID + d0 * NH;
            __half* phi = Cbase + (size_t)rhi * HID + d0 * NH;
            plo[0]  = __float2half_rn(acc_o[mt][nt2][0] * ilo);
            plo[NH] = __float2half_rn(acc_o[mt][nt2][1] * ilo);
            phi[0]  = __float2half_rn(acc_o[mt][nt2][2] * ihi);
            phi[NH] = __float2half_rn(acc_o[mt][nt2][3] * ihi);
        }
    }
}

// ---------------- host launch ----------------
extern "C" void kernel_launch(void* const* d_in, const int* in_sizes, int n_in,
                              void* d_out, int out_size)
{
    const float* x   = (const float*)d_in[0];
    const float* Wq  = (const float*)d_in[1];
    const float* Wk  = (const float*)d_in[2];
    // d_in[3] = Wv: unused (ctx contracts with K in the reference)
    const float* Wo  = (const float*)d_in[4];
    const float* W1  = (const float*)d_in[5];
    const float* b1  = (const float*)d_in[6];
    const float* W2  = (const float*)d_in[7];
    const float* b2  = (const float*)d_in[8];
    const float* g1  = (const float*)d_in[9];
    const float* be1 = (const float*)d_in[10];
    const float* g2  = (const float*)d_in[11];
    const float* be2 = (const float*)d_in[12];
    float* out = (float*)d_out;

    float  *QK, *Qh, *Kh, *x1f;
    __half *xh, *Ctxh, *x1h, *Hfh, *Wqkh, *Worh, *W1h, *W2h;
    cudaGetSymbolAddress((void**)&QK,  g_QK);
    cudaGetSymbolAddress((void**)&Qh,  g_Qh);
    cudaGetSymbolAddress((void**)&Kh,  g_Kh);
    cudaGetSymbolAddress((void**)&x1f, g_x1f);
    cudaGetSymbolAddress((void**)&xh,  g_xh);
    cudaGetSymbolAddress((void**)&Ctxh,g_Ctxh);
    cudaGetSymbolAddress((void**)&x1h, g_x1h);
    cudaGetSymbolAddress((void**)&Hfh, g_Hfh);
    cudaGetSymbolAddress((void**)&Wqkh,g_Wqkh);
    cudaGetSymbolAddress((void**)&Worh,g_Worh);
    cudaGetSymbolAddress((void**)&W1h, g_W1h);
    cudaGetSymbolAddress((void**)&W2h, g_W2h);

    static bool attrs_set = false;
    if (!attrs_set) {
        cudaFuncSetAttribute(attn_fused, cudaFuncAttributeMaxDynamicSharedMemorySize, ATTN_SMEM_BYTES);
        cudaFuncSetAttribute(gemm_h<EPI_NONE, false>,     cudaFuncAttributeMaxDynamicSharedMemorySize, GEMM_SMEM_BYTES);
        cudaFuncSetAttribute(gemm_h<EPI_BIAS_GELU, true>, cudaFuncAttributeMaxDynamicSharedMemorySize, GEMM_SMEM_BYTES);
        cudaFuncSetAttribute(gemm_h_splitk,               cudaFuncAttributeMaxDynamicSharedMemorySize, GEMM_SMEM_BYTES);
        attrs_set = true;
    }

    const int nperm = MROWS * HID;
    const int n4 = MROWS * HID / 4;
    const dim3 tb(32, 8);

    // ---- operand conversion: weights transpose->fp16, x->fp16 ----
    transpose_h_k<<<dim3(HID / 32, HID / 32), tb>>>(Wq, Wqkh, HID, HID);
    transpose_h_k<<<dim3(HID / 32, HID / 32), tb>>>(Wk, Wqkh + (size_t)HID * HID, HID, HID);
    transpose_h_k<<<dim3(HID / 32, HID / 32), tb>>>(Wo, Worh, HID, HID);
    transpose_h_k<<<dim3(MLPD / 32, HID / 32), tb>>>(W1, W1h, HID, MLPD);
    transpose_h_k<<<dim3(HID / 32, MLPD / 32), tb>>>(W2, W2h, MLPD, HID);
    tohalf_k<<<(n4 + 255) / 256, 256>>>((const float4*)x, (__half2*)xh, n4);

    // ---- QK merged GEMM (fp16 mma): [Q|K] = xh @ [Wq|Wk] ----
    gemm_h<EPI_NONE, false><<<dim3(2 * HID / 128, MROWS / 128), 256, GEMM_SMEM_BYTES>>>(
        xh, Wqkh, QK, nullptr, MROWS, 2 * HID, HID);

    to_head2_k<<<(nperm + 255) / 256, 256>>>(QK, Qh, Kh);

    // ---- fused flash attention (tf32): writes fp16 interleaved Ctx directly ----
    attn_fused<<<dim3(LSEQ / 128, NHEADS_TOT), 256, ATTN_SMEM_BYTES>>>(Qh, Kh, Ctxh);

    // ---- Wo GEMM: fp16 split-K=2 partials -> fused reduce(+x) + LN -> x1f/x1h ----
    gemm_h_splitk<<<dim3(HID / 128, MROWS / 128, 2), 256, GEMM_SMEM_BYTES>>>(
        Ctxh, Worh, QK, MROWS, HID, HID, HID / 2);
    layernorm_fused_k<false, true><<<MROWS, 256>>>(QK, nullptr, x, g1, be1, x1f, x1h);

    // ---- MLP (fp16 mma) ----
    gemm_h<EPI_BIAS_GELU, true><<<dim3(MLPD / 128, MROWS / 128), 256, GEMM_SMEM_BYTES>>>(
        x1h, W1h, Hfh, b1, MROWS, MLPD, HID);
    gemm_h_splitk<<<dim3(HID / 128, MROWS / 128, 2), 256, GEMM_SMEM_BYTES>>>(
        Hfh, W2h, QK, MROWS, HID, MLPD, MLPD / 2);
    layernorm_fused_k<true, false><<<MROWS, 256>>>(QK, b2, x1f, g2, be2, out, nullptr);
}

// round 13
// speedup vs baseline: 1.5041x; 1.1148x over previous
#include <cuda_runtime.h>
#include <cuda_fp16.h>
#include <math.h>
#include <stdint.h>

#define BATCH 8
#define LSEQ  1024
#define HID   768
#define NH    12
#define DH    64
#define MLPD  3072
#define MROWS (BATCH*LSEQ)    // 8192
#define NHEADS_TOT (BATCH*NH) // 96

// ---------------- static scratch ----------------
__device__ float  g_QK [(size_t)MROWS*2*HID];  // split-K partials
__device__ float  g_x1f[MROWS*HID];
__device__ __half g_QKh[(size_t)MROWS*2*HID];
__device__ __half g_Qhh[MROWS*HID];
__device__ __half g_Khh[MROWS*HID];
__device__ __half g_xh  [MROWS*HID];
__device__ __half g_Ctxh[MROWS*HID];
__device__ __half g_x1h [MROWS*HID];
__device__ __half g_Hfh [(size_t)MROWS*MLPD];
__device__ __half g_Wqkh[(size_t)2*HID*HID];   // [1536][768] N-major
__device__ __half g_Worh[HID*HID];
__device__ __half g_W1h [(size_t)MLPD*HID];
__device__ __half g_W2h [(size_t)HID*MLPD];

// ---------------- helpers ----------------
__device__ __forceinline__ float gelu_f(float v) {
    return 0.5f * v * (1.0f + erff(v * 0.7071067811865475f));
}

__device__ __forceinline__ void mma_f16(float* d, const uint32_t* a, const uint32_t* b) {
    asm volatile(
        "mma.sync.aligned.m16n8k16.row.col.f32.f16.f16.f32 "
        "{%0,%1,%2,%3}, {%4,%5,%6,%7}, {%8,%9}, {%0,%1,%2,%3};\n"
        : "+f"(d[0]), "+f"(d[1]), "+f"(d[2]), "+f"(d[3])
        : "r"(a[0]), "r"(a[1]), "r"(a[2]), "r"(a[3]),
          "r"(b[0]), "r"(b[1]));
}

__device__ __forceinline__ void ldsm4(uint32_t* r, uint32_t addr) {
    asm volatile("ldmatrix.sync.aligned.m8n8.x4.shared.b16 {%0,%1,%2,%3}, [%4];"
        : "=r"(r[0]), "=r"(r[1]), "=r"(r[2]), "=r"(r[3]) : "r"(addr));
}

__device__ __forceinline__ void cp16(uint32_t dst, const void* src) {
    asm volatile("cp.async.cg.shared.global [%0], [%1], 16;\n" :: "r"(dst), "l"(src));
}
__device__ __forceinline__ void cp_commit() {
    asm volatile("cp.async.commit_group;\n");
}
template<int N>
__device__ __forceinline__ void cp_wait() {
    asm volatile("cp.async.wait_group %0;\n" :: "n"(N));
}

enum { EPI_NONE = 0, EPI_BIAS_GELU = 2 };

// ---------------- FP16 tensor-core GEMM: C = A(MxK) @ Bt(NxK)^T ----------------
#define HS_STR 40
#define STAGES 4
#define TILE_HALVES (128 * HS_STR)
#define TILE_BYTES  (TILE_HALVES * 2)
#define GEMM_SMEM_BYTES (STAGES * 2 * TILE_BYTES)

#define GEMM_CORE_LOOP(aBase, bBase) \
    _Pragma("unroll") \
    for (int kk = 0; kk < 32; kk += 16) { \
        uint32_t a[4][4], b[4][2]; \
        _Pragma("unroll") \
        for (int mt = 0; mt < 4; mt++) \
            ldsm4(a[mt], (aBase) + (uint32_t)((wm + mt * 16 + rl16) * HS_STR + kk + ko8) * 2); \
        _Pragma("unroll") \
        for (int nb = 0; nb < 2; nb++) { \
            uint32_t t4[4]; \
            ldsm4(t4, (bBase) + (uint32_t)((wn + nb * 16 + brow) * HS_STR + kk + bko) * 2); \
            b[2 * nb][0]     = t4[0]; \
            b[2 * nb][1]     = t4[1]; \
            b[2 * nb + 1][0] = t4[2]; \
            b[2 * nb + 1][1] = t4[3]; \
        } \
        _Pragma("unroll") \
        for (int mt = 0; mt < 4; mt++) \
            _Pragma("unroll") \
            for (int nt = 0; nt < 4; nt++) \
                mma_f16(acc[mt][nt], a[mt], b[nt]); \
    }

template<int EPI, bool OUTH>
__global__ __launch_bounds__(256, 2) void gemm_h(
    const __half* __restrict__ A, const __half* __restrict__ Bt, void* __restrict__ Cv,
    const float* __restrict__ bias, int M, int N, int K)
{
    extern __shared__ __half hsm[];
    const uint32_t sA = (uint32_t)__cvta_generic_to_shared(hsm);
    const uint32_t sB = sA + STAGES * TILE_BYTES;

    const int tid  = threadIdx.x;
    const int lane = tid & 31;
    const int warp = tid >> 5;
    const int grp  = lane >> 2;
    const int tg   = lane & 3;
    const int wm   = (warp >> 2) * 64;
    const int wn   = (warp & 3) * 32;
    const int bx   = blockIdx.x;
    const int by   = blockIdx.y;

    const int rl16 = lane & 15;
    const int ko8  = (lane >> 4) << 3;
    const int brow = (lane & 7) + ((lane >> 4) << 3);
    const int bko  = ((lane >> 3) & 1) << 3;

    const __half* Abase = A  + (size_t)(by * 128) * K;
    const __half* Bbase = Bt + (size_t)(bx * 128) * K;

    float acc[4][4][4];
    #pragma unroll
    for (int i = 0; i < 4; i++)
        #pragma unroll
        for (int j = 0; j < 4; j++)
            #pragma unroll
            for (int r = 0; r < 4; r++) acc[i][j][r] = 0.0f;

    const int nt_ = K >> 5;

    auto issue = [&](int t) {
        const int st = t & (STAGES - 1);
        const int k0 = t << 5;
        const uint32_t aoff = sA + st * TILE_BYTES;
        const uint32_t boff = sB + st * TILE_BYTES;
        #pragma unroll
        for (int i = 0; i < 2; i++) {
            const int c = tid + 256 * i;
            const int r = c >> 2, ch = (c & 3) * 8;
            cp16(aoff + (uint32_t)(r * HS_STR + ch) * 2, Abase + (size_t)r * K + k0 + ch);
            cp16(boff + (uint32_t)(r * HS_STR + ch) * 2, Bbase + (size_t)r * K + k0 + ch);
        }
        cp_commit();
    };

    #pragma unroll
    for (int t = 0; t < STAGES - 1; t++) issue(t);

    for (int t = 0; t < nt_; t++) {
        cp_wait<STAGES - 2>();
        __syncthreads();
        const int cur = t & (STAGES - 1);
        const uint32_t aBase = sA + cur * TILE_BYTES;
        const uint32_t bBase = sB + cur * TILE_BYTES;
        GEMM_CORE_LOOP(aBase, bBase)
        if (t + STAGES - 1 < nt_) issue(t + STAGES - 1);
        else cp_commit();
    }

    #pragma unroll
    for (int mt = 0; mt < 4; mt++) {
        #pragma unroll
        for (int nt = 0; nt < 4; nt++) {
            const int r0 = by * 128 + wm + mt * 16 + grp;
            const int c0 = bx * 128 + wn + nt * 8 + tg * 2;
            float v0 = acc[mt][nt][0], v1 = acc[mt][nt][1];
            float v2 = acc[mt][nt][2], v3 = acc[mt][nt][3];
            if (EPI == EPI_BIAS_GELU) {
                const float2 bv = *(const float2*)&bias[c0];
                v0 = gelu_f(v0 + bv.x); v1 = gelu_f(v1 + bv.y);
                v2 = gelu_f(v2 + bv.x); v3 = gelu_f(v3 + bv.y);
            }
            if (OUTH) {
                __half* Ch = (__half*)Cv;
                *(__half2*)&Ch[(size_t)r0 * N + c0] = __floats2half2_rn(v0, v1);
                *(__half2*)&Ch[(size_t)(r0 + 8) * N + c0] = __floats2half2_rn(v2, v3);
            } else {
                float* Cf = (float*)Cv;
                float2 w0 = {v0, v1}, w1 = {v2, v3};
                *(float2*)&Cf[(size_t)r0 * N + c0] = w0;
                *(float2*)&Cf[(size_t)(r0 + 8) * N + c0] = w1;
            }
        }
    }
}

// ---------------- FP16 split-K=2 partial GEMM ----------------
__global__ __launch_bounds__(256, 2) void gemm_h_splitk(
    const __half* __restrict__ A, const __half* __restrict__ Bt, float* __restrict__ Cp,
    int M, int N, int ldk, int Khalf)
{
    extern __shared__ __half hsm[];
    const uint32_t sA = (uint32_t)__cvta_generic_to_shared(hsm);
    const uint32_t sB = sA + STAGES * TILE_BYTES;

    const int tid  = threadIdx.x;
    const int lane = tid & 31;
    const int warp = tid >> 5;
    const int grp  = lane >> 2;
    const int tg   = lane & 3;
    const int wm   = (warp >> 2) * 64;
    const int wn   = (warp & 3) * 32;
    const int bx   = blockIdx.x;
    const int by   = blockIdx.y;
    const int z    = blockIdx.z;

    const int rl16 = lane & 15;
    const int ko8  = (lane >> 4) << 3;
    const int brow = (lane & 7) + ((lane >> 4) << 3);
    const int bko  = ((lane >> 3) & 1) << 3;

    const __half* Abase = A  + (size_t)(by * 128) * ldk + (size_t)z * Khalf;
    const __half* Bbase = Bt + (size_t)(bx * 128) * ldk + (size_t)z * Khalf;

    float acc[4][4][4];
    #pragma unroll
    for (int i = 0; i < 4; i++)
        #pragma unroll
        for (int j = 0; j < 4; j++)
            #pragma unroll
            for (int r = 0; r < 4; r++) acc[i][j][r] = 0.0f;

    const int nt_ = Khalf >> 5;

    auto issue = [&](int t) {
        const int st = t & (STAGES - 1);
        const int k0 = t << 5;
        const uint32_t aoff = sA + st * TILE_BYTES;
        const uint32_t boff = sB + st * TILE_BYTES;
        #pragma unroll
        for (int i = 0; i < 2; i++) {
            const int c = tid + 256 * i;
            const int r = c >> 2, ch = (c & 3) * 8;
            cp16(aoff + (uint32_t)(r * HS_STR + ch) * 2, Abase + (size_t)r * ldk + k0 + ch);
            cp16(boff + (uint32_t)(r * HS_STR + ch) * 2, Bbase + (size_t)r * ldk + k0 + ch);
        }
        cp_commit();
    };

    #pragma unroll
    for (int t = 0; t < STAGES - 1; t++) issue(t);

    for (int t = 0; t < nt_; t++) {
        cp_wait<STAGES - 2>();
        __syncthreads();
        const int cur = t & (STAGES - 1);
        const uint32_t aBase = sA + cur * TILE_BYTES;
        const uint32_t bBase = sB + cur * TILE_BYTES;
        GEMM_CORE_LOOP(aBase, bBase)
        if (t + STAGES - 1 < nt_) issue(t + STAGES - 1);
        else cp_commit();
    }

    float* Cz = Cp + (size_t)z * M * N;
    #pragma unroll
    for (int mt = 0; mt < 4; mt++) {
        #pragma unroll
        for (int nt = 0; nt < 4; nt++) {
            const int r0 = by * 128 + wm + mt * 16 + grp;
            const int c0 = bx * 128 + wn + nt * 8 + tg * 2;
            float2 w0 = {acc[mt][nt][0], acc[mt][nt][1]};
            float2 w1 = {acc[mt][nt][2], acc[mt][nt][3]};
            *(float2*)&Cz[(size_t)r0 * N + c0] = w0;
            *(float2*)&Cz[(size_t)(r0 + 8) * N + c0] = w1;
        }
    }
}

// ---------------- fused split-K reduce + layernorm ----------------
template<bool BIAS, bool HOUT>
__global__ __launch_bounds__(256) void layernorm_fused_k(
    const float* __restrict__ p, const float* __restrict__ bias,
    const float* __restrict__ res, const float* __restrict__ g,
    const float* __restrict__ be, float* __restrict__ Yf, __half* __restrict__ Yh)
{
    const int row = blockIdx.x;
    const float* p0 = p + (size_t)row * HID;
    const float* p1 = p + (size_t)MROWS * HID + (size_t)row * HID;
    const float* r  = res + (size_t)row * HID;
    const int tid = threadIdx.x;
    __shared__ float vbuf[HID];
    __shared__ float shs[8], shss[8];

    float s = 0.0f, ss = 0.0f;
    for (int c = tid; c < HID; c += 256) {
        float v = p0[c] + p1[c] + r[c];
        if (BIAS) v += bias[c];
        vbuf[c] = v;
        s += v;
        ss = fmaf(v, v, ss);
    }
    #pragma unroll
    for (int o = 16; o; o >>= 1) {
        s  += __shfl_xor_sync(0xffffffffu, s, o);
        ss += __shfl_xor_sync(0xffffffffu, ss, o);
    }
    if ((tid & 31) == 0) { shs[tid >> 5] = s; shss[tid >> 5] = ss; }
    __syncthreads();
    if (tid == 0) {
        float a = 0.0f, b = 0.0f;
        #pragma unroll
        for (int i = 0; i < 8; i++) { a += shs[i]; b += shss[i]; }
        shs[0] = a; shss[0] = b;
    }
    __syncthreads();
    const float mu  = shs[0]  * (1.0f / HID);
    const float var = shss[0] * (1.0f / HID) - mu * mu;
    const float inv = rsqrtf(var + 1e-5f);
    for (int c = tid; c < HID; c += 256) {
        float v = (vbuf[c] - mu) * inv * g[c] + be[c];
        Yf[(size_t)row * HID + c] = v;
        if (HOUT) Yh[(size_t)row * HID + c] = __float2half_rn(v);
    }
}

// ---------------- operand conversion ----------------
__global__ void transpose_h_k(const float* __restrict__ W, __half* __restrict__ Wt,
                              int K, int N) {
    __shared__ float tb[32][33];
    const int n0 = blockIdx.x * 32;
    const int k0 = blockIdx.y * 32;
    const int tx = threadIdx.x, ty = threadIdx.y;
    #pragma unroll
    for (int j = ty; j < 32; j += 8)
        tb[j][tx] = W[(size_t)(k0 + j) * N + n0 + tx];
    __syncthreads();
    #pragma unroll
    for (int j = ty; j < 32; j += 8)
        Wt[(size_t)(n0 + j) * K + k0 + tx] = __float2half_rn(tb[tx][j]);
}

__global__ void tohalf_k(const float4* __restrict__ in, __half2* __restrict__ out, int n4) {
    int i = blockIdx.x * blockDim.x + threadIdx.x;
    if (i >= n4) return;
    float4 v = in[i];
    out[2 * i]     = __floats2half2_rn(v.x, v.y);
    out[2 * i + 1] = __floats2half2_rn(v.z, v.w);
}

// ---------------- permute to head-major (half -> half, Q scaled by 1/8) ----------------
__global__ void to_head2_k(const __half* __restrict__ QK,
                           __half* __restrict__ Qh, __half* __restrict__ Kh) {
    int idx = blockIdx.x * blockDim.x + threadIdx.x;
    if (idx >= MROWS * HID) return;
    int d = idx & 63;
    int l = (idx >> 6) & 1023;
    int z = idx >> 16;
    int n = z % NH, b = z / NH;
    const size_t src = (size_t)(b * LSEQ + l) * (2 * HID) + d * NH + n;
    Qh[idx] = __float2half_rn(__half2float(QK[src]) * 0.125f);   // exact pow2 scale
    Kh[idx] = QK[src + HID];
}

// ---------------- FP16 fused flash attention ----------------
// Q/K half, head-major. S = Q@K^T (fp16 mma), streaming softmax (fp32),
// O += P@K via transposed K copy in smem. Writes fp16 interleaved Ctx.
#define AQ_STR  72    // halves per Q/K row (64 + 8 pad)
#define AKT_STR 136   // halves per Kst/Ps row (128 + 8 pad)
#define ATTN_HALVES (128*AQ_STR + 128*AQ_STR + 64*AKT_STR + 128*AKT_STR)
#define ATTN_FLOATS (128 + 128 + 512 + 512)
#define ATTN_SMEM_BYTES (ATTN_HALVES * 2 + ATTN_FLOATS * 4)

__global__ __launch_bounds__(256) void attn_fused(
    const __half* __restrict__ Qh, const __half* __restrict__ Kh, __half* __restrict__ Ctx)
{
    extern __shared__ __half asm_[];
    __half* Qs  = asm_;                       // [128][AQ_STR]
    __half* Ks  = Qs + 128 * AQ_STR;          // [128][AQ_STR]  (key-major)
    __half* Kst = Ks + 128 * AQ_STR;          // [64][AKT_STR]  (d-major, transposed)
    __half* Ps  = Kst + 64 * AKT_STR;         // [128][AKT_STR]
    float* Mrow = (float*)(Ps + 128 * AKT_STR);
    float* Srow = Mrow + 128;
    float* red1 = Srow + 128;
    float* red2 = red1 + 512;

    const uint32_t qA  = (uint32_t)__cvta_generic_to_shared(Qs);
    const uint32_t kA  = (uint32_t)__cvta_generic_to_shared(Ks);
    const uint32_t ktA = (uint32_t)__cvta_generic_to_shared(Kst);
    const uint32_t pA  = (uint32_t)__cvta_generic_to_shared(Ps);

    const int z   = blockIdx.y;
    const int l0  = blockIdx.x * 128;
    const int tid = threadIdx.x;
    const int lane = tid & 31;
    const int warp = tid >> 5;
    const int grp  = lane >> 2;
    const int tg   = lane & 3;
    const int wm   = (warp >> 2) * 64;   // S/O row offset
    const int wn   = (warp & 3) * 32;    // S col offset
    const int wn2  = (warp & 3) * 16;    // O col offset
    const int wc   = warp & 3;

    const int rl16 = lane & 15;
    const int ko8  = (lane >> 4) << 3;
    const int brow = (lane & 7) + ((lane >> 4) << 3);
    const int bko  = ((lane >> 3) & 1) << 3;

    const __half* Qbase = Qh + ((size_t)z * LSEQ + l0) * DH;
    const __half* Kbase = Kh + (size_t)z * LSEQ * DH;

    if (tid < 128) { Mrow[tid] = -3.0e38f; Srow[tid] = 0.0f; }

    // stage Q tile: 8192 halves as 2048 x half4
    #pragma unroll
    for (int i = 0; i < 8; i++) {
        const int f = tid + 256 * i;
        const int r = f >> 4, c4 = (f & 15) * 4;
        uint2 v = *(const uint2*)(Qbase + r * DH + c4);
        *(uint2*)&Qs[r * AQ_STR + c4] = v;
    }

    float acc_o[4][2][4];
    #pragma unroll
    for (int i = 0; i < 4; i++)
        #pragma unroll
        for (int j = 0; j < 2; j++)
            #pragma unroll
            for (int r = 0; r < 4; r++) acc_o[i][j][r] = 0.0f;

    __syncthreads();

    for (int mtile = 0; mtile < LSEQ / 128; mtile++) {
        // stage K tile (both layouts)
        const __half* Kt = Kbase + (size_t)mtile * 128 * DH;
        #pragma unroll
        for (int i = 0; i < 8; i++) {
            const int f = tid + 256 * i;
            const int r = f >> 4, c4 = (f & 15) * 4;
            uint2 v = *(const uint2*)(Kt + r * DH + c4);
            *(uint2*)&Ks[r * AQ_STR + c4] = v;
            __half h4[4];
            *(uint2*)h4 = v;
            #pragma unroll
            for (int j = 0; j < 4; j++)
                Kst[(c4 + j) * AKT_STR + r] = h4[j];
        }
        __syncthreads();

        // ---- S = Q @ K^T (fp16 mma, K=64) ----
        float s[4][4][4];
        #pragma unroll
        for (int i = 0; i < 4; i++)
            #pragma unroll
            for (int j = 0; j < 4; j++)
                #pragma unroll
                for (int r = 0; r < 4; r++) s[i][j][r] = 0.0f;

        #pragma unroll
        for (int kk = 0; kk < DH; kk += 16) {
            uint32_t a[4][4], b[4][2];
            #pragma unroll
            for (int mt = 0; mt < 4; mt++)
                ldsm4(a[mt], qA + (uint32_t)((wm + mt * 16 + rl16) * AQ_STR + kk + ko8) * 2);
            #pragma unroll
            for (int nb = 0; nb < 2; nb++) {
                uint32_t t4[4];
                ldsm4(t4, kA + (uint32_t)((wn + nb * 16 + brow) * AQ_STR + kk + bko) * 2);
                b[2 * nb][0]     = t4[0];
                b[2 * nb][1]     = t4[1];
                b[2 * nb + 1][0] = t4[2];
                b[2 * nb + 1][1] = t4[3];
            }
            #pragma unroll
            for (int mt = 0; mt < 4; mt++)
                #pragma unroll
                for (int nt = 0; nt < 4; nt++)
                    mma_f16(s[mt][nt], a[mt], b[nt]);
        }

        // ---- Phase A: per-warp row max ----
        #pragma unroll
        for (int mt = 0; mt < 4; mt++) {
            float mlo = -3.0e38f, mhi = -3.0e38f;
            #pragma unroll
            for (int nt = 0; nt < 4; nt++) {
                mlo = fmaxf(mlo, fmaxf(s[mt][nt][0], s[mt][nt][1]));
                mhi = fmaxf(mhi, fmaxf(s[mt][nt][2], s[mt][nt][3]));
            }
            mlo = fmaxf(mlo, __shfl_xor_sync(0xffffffffu, mlo, 1));
            mlo = fmaxf(mlo, __shfl_xor_sync(0xffffffffu, mlo, 2));
            mhi = fmaxf(mhi, __shfl_xor_sync(0xffffffffu, mhi, 1));
            mhi = fmaxf(mhi, __shfl_xor_sync(0xffffffffu, mhi, 2));
            if (tg == 0) {
                red1[(wm + mt * 16 + grp) * 4 + wc]     = mlo;
                red1[(wm + mt * 16 + grp + 8) * 4 + wc] = mhi;
            }
        }
        __syncthreads();

        // ---- Phase B: P = exp(s - M) (fp16 store), row sums, rescale O ----
        float newlo[4], newhi[4], scllo[4], sclhi[4];
        #pragma unroll
        for (int mt = 0; mt < 4; mt++) {
            const int rlo = wm + mt * 16 + grp;
            const int rhi = rlo + 8;
            float4 v1 = *(const float4*)&red1[rlo * 4];
            float4 v2 = *(const float4*)&red1[rhi * 4];
            float tlo = fmaxf(fmaxf(v1.x, v1.y), fmaxf(v1.z, v1.w));
            float thi = fmaxf(fmaxf(v2.x, v2.y), fmaxf(v2.z, v2.w));
            float oldlo = Mrow[rlo], oldhi = Mrow[rhi];
            float nlo = fmaxf(oldlo, tlo), nhi = fmaxf(oldhi, thi);
            newlo[mt] = nlo; newhi[mt] = nhi;
            scllo[mt] = __expf(oldlo - nlo);
            sclhi[mt] = __expf(oldhi - nhi);

            float pslo = 0.0f, pshi = 0.0f;
            #pragma unroll
            for (int nt = 0; nt < 4; nt++) {
                const int c = wn + nt * 8 + 2 * tg;
                float p0 = __expf(s[mt][nt][0] - nlo);
                float p1 = __expf(s[mt][nt][1] - nlo);
                float p2 = __expf(s[mt][nt][2] - nhi);
                float p3 = __expf(s[mt][nt][3] - nhi);
                *(__half2*)&Ps[rlo * AKT_STR + c] = __floats2half2_rn(p0, p1);
                *(__half2*)&Ps[rhi * AKT_STR + c] = __floats2half2_rn(p2, p3);
                pslo += p0 + p1;
                pshi += p2 + p3;
            }
            pslo += __shfl_xor_sync(0xffffffffu, pslo, 1);
            pslo += __shfl_xor_sync(0xffffffffu, pslo, 2);
            pshi += __shfl_xor_sync(0xffffffffu, pshi, 1);
            pshi += __shfl_xor_sync(0xffffffffu, pshi, 2);
            if (tg == 0) {
                red2[rlo * 4 + wc] = pslo;
                red2[rhi * 4 + wc] = pshi;
            }
            #pragma unroll
            for (int nt2 = 0; nt2 < 2; nt2++) {
                acc_o[mt][nt2][0] *= scllo[mt];
                acc_o[mt][nt2][1] *= scllo[mt];
                acc_o[mt][nt2][2] *= sclhi[mt];
                acc_o[mt][nt2][3] *= sclhi[mt];
            }
        }
        __syncthreads();

        // ---- Phase C: update M / Sum ----
        if (wc == 0 && tg == 0) {
            #pragma unroll
            for (int mt = 0; mt < 4; mt++) {
                const int rlo = wm + mt * 16 + grp;
                const int rhi = rlo + 8;
                float4 w1 = *(const float4*)&red2[rlo * 4];
                float4 w2 = *(const float4*)&red2[rhi * 4];
                Srow[rlo] = Srow[rlo] * scllo[mt] + (w1.x + w1.y + w1.z + w1.w);
                Srow[rhi] = Srow[rhi] * sclhi[mt] + (w2.x + w2.y + w2.z + w2.w);
                Mrow[rlo] = newlo[mt];
                Mrow[rhi] = newhi[mt];
            }
        }

        // ---- O += P @ Ktile (fp16 mma, K=128, B from transposed Kst) ----
        #pragma unroll
        for (int kk = 0; kk < 128; kk += 16) {
            uint32_t a[4][4], b[2][2];
            #pragma unroll
            for (int mt = 0; mt < 4; mt++)
                ldsm4(a[mt], pA + (uint32_t)((wm + mt * 16 + rl16) * AKT_STR + kk + ko8) * 2);
            {
                uint32_t t4[4];
                ldsm4(t4, ktA + (uint32_t)((wn2 + brow) * AKT_STR + kk + bko) * 2);
                b[0][0] = t4[0]; b[0][1] = t4[1];
                b[1][0] = t4[2]; b[1][1] = t4[3];
            }
            #pragma unroll
            for (int mt = 0; mt < 4; mt++)
                #pragma unroll
                for (int nt2 = 0; nt2 < 2; nt2++)
                    mma_f16(acc_o[mt][nt2], a[mt], b[nt2]);
        }
        __syncthreads();
    }

    // ---- epilogue: normalize, fp16-round, scatter to interleaved Ctx ----
    const int bq = z / NH;
    const int nh = z % NH;
    __half* Cbase = Ctx + ((size_t)(bq * LSEQ + l0)) * HID + nh;
    #pragma unroll
    for (int mt = 0; mt < 4; mt++) {
        const int rlo = wm + mt * 16 + grp;
        const int rhi = rlo + 8;
        const float ilo = 1.0f / Srow[rlo];
        const float ihi = 1.0f / Srow[rhi];
        #pragma unroll
        for (int nt2 = 0; nt2 < 2; nt2++) {
            const int d0 = wn2 + nt2 * 8 + 2 * tg;
            __half* plo = Cbase + (size_t)rlo * HID + d0 * NH;
            __half* phi = Cbase + (size_t)rhi * HID + d0 * NH;
            plo[0]  = __float2half_rn(acc_o[mt][nt2][0] * ilo);
            plo[NH] = __float2half_rn(acc_o[mt][nt2][1] * ilo);
            phi[0]  = __float2half_rn(acc_o[mt][nt2][2] * ihi);
            phi[NH] = __float2half_rn(acc_o[mt][nt2][3] * ihi);
        }
    }
}

// ---------------- host launch ----------------
extern "C" void kernel_launch(void* const* d_in, const int* in_sizes, int n_in,
                              void* d_out, int out_size)
{
    const float* x   = (const float*)d_in[0];
    const float* Wq  = (const float*)d_in[1];
    const float* Wk  = (const float*)d_in[2];
    // d_in[3] = Wv: unused (ctx contracts with K in the reference)
    const float* Wo  = (const float*)d_in[4];
    const float* W1  = (const float*)d_in[5];
    const float* b1  = (const float*)d_in[6];
    const float* W2  = (const float*)d_in[7];
    const float* b2  = (const float*)d_in[8];
    const float* g1  = (const float*)d_in[9];
    const float* be1 = (const float*)d_in[10];
    const float* g2  = (const float*)d_in[11];
    const float* be2 = (const float*)d_in[12];
    float* out = (float*)d_out;

    float  *QK, *x1f;
    __half *QKh, *Qhh, *Khh, *xh, *Ctxh, *x1h, *Hfh, *Wqkh, *Worh, *W1h, *W2h;
    cudaGetSymbolAddress((void**)&QK,  g_QK);
    cudaGetSymbolAddress((void**)&x1f, g_x1f);
    cudaGetSymbolAddress((void**)&QKh, g_QKh);
    cudaGetSymbolAddress((void**)&Qhh, g_Qhh);
    cudaGetSymbolAddress((void**)&Khh, g_Khh);
    cudaGetSymbolAddress((void**)&xh,  g_xh);
    cudaGetSymbolAddress((void**)&Ctxh,g_Ctxh);
    cudaGetSymbolAddress((void**)&x1h, g_x1h);
    cudaGetSymbolAddress((void**)&Hfh, g_Hfh);
    cudaGetSymbolAddress((void**)&Wqkh,g_Wqkh);
    cudaGetSymbolAddress((void**)&Worh,g_Worh);
    cudaGetSymbolAddress((void**)&W1h, g_W1h);
    cudaGetSymbolAddress((void**)&W2h, g_W2h);

    static bool attrs_set = false;
    if (!attrs_set) {
        cudaFuncSetAttribute(attn_fused, cudaFuncAttributeMaxDynamicSharedMemorySize, ATTN_SMEM_BYTES);
        cudaFuncSetAttribute(gemm_h<EPI_NONE, true>,      cudaFuncAttributeMaxDynamicSharedMemorySize, GEMM_SMEM_BYTES);
        cudaFuncSetAttribute(gemm_h<EPI_BIAS_GELU, true>, cudaFuncAttributeMaxDynamicSharedMemorySize, GEMM_SMEM_BYTES);
        cudaFuncSetAttribute(gemm_h_splitk,               cudaFuncAttributeMaxDynamicSharedMemorySize, GEMM_SMEM_BYTES);
        attrs_set = true;
    }

    const int nperm = MROWS * HID;
    const int n4 = MROWS * HID / 4;
    const dim3 tb(32, 8);

    // ---- operand conversion: weights transpose->fp16, x->fp16 ----
    transpose_h_k<<<dim3(HID / 32, HID / 32), tb>>>(Wq, Wqkh, HID, HID);
    transpose_h_k<<<dim3(HID / 32, HID / 32), tb>>>(Wk, Wqkh + (size_t)HID * HID, HID, HID);
    transpose_h_k<<<dim3(HID / 32, HID / 32), tb>>>(Wo, Worh, HID, HID);
    transpose_h_k<<<dim3(MLPD / 32, HID / 32), tb>>>(W1, W1h, HID, MLPD);
    transpose_h_k<<<dim3(HID / 32, MLPD / 32), tb>>>(W2, W2h, MLPD, HID);
    tohalf_k<<<(n4 + 255) / 256, 256>>>((const float4*)x, (__half2*)xh, n4);

    // ---- QK merged GEMM (fp16 -> fp16 output) ----
    gemm_h<EPI_NONE, true><<<dim3(2 * HID / 128, MROWS / 128), 256, GEMM_SMEM_BYTES>>>(
        xh, Wqkh, QKh, nullptr, MROWS, 2 * HID, HID);

    to_head2_k<<<(nperm + 255) / 256, 256>>>(QKh, Qhh, Khh);

    // ---- FP16 fused flash attention ----
    attn_fused<<<dim3(LSEQ / 128, NHEADS_TOT), 256, ATTN_SMEM_BYTES>>>(Qhh, Khh, Ctxh);

    // ---- Wo GEMM: fp16 split-K=2 -> fused reduce(+x) + LN -> x1f/x1h ----
    gemm_h_splitk<<<dim3(HID / 128, MROWS / 128, 2), 256, GEMM_SMEM_BYTES>>>(
        Ctxh, Worh, QK, MROWS, HID, HID, HID / 2);
    layernorm_fused_k<false, true><<<MROWS, 256>>>(QK, nullptr, x, g1, be1, x1f, x1h);

    // ---- MLP (fp16 mma) ----
    gemm_h<EPI_BIAS_GELU, true><<<dim3(MLPD / 128, MROWS / 128), 256, GEMM_SMEM_BYTES>>>(
        x1h, W1h, Hfh, b1, MROWS, MLPD, HID);
    gemm_h_splitk<<<dim3(HID / 128, MROWS / 128, 2), 256, GEMM_SMEM_BYTES>>>(
        Hfh, W2h, QK, MROWS, HID, MLPD, MLPD / 2);
    layernorm_fused_k<true, false><<<MROWS, 256>>>(QK, b2, x1f, g2, be2, out, nullptr);
}